// round 10
// baseline (speedup 1.0000x reference)
#include <cuda_runtime.h>
#include <cuda_fp16.h>
#include <cstdint>

#define D_ 512
#define P_ 1024
#define E_ 256
#define OUT_ 500

// ---------------- device scratch ----------------
__device__ __half g_posth[P_ * D_];
__device__ __half g_emojih[E_ * D_];
__device__ __half g_k1wh[512 * 512];
__device__ __half g_k2wh[512 * 512];
__device__ __half g_l1ph[512 * 512];
__device__ __half g_l1eh[512 * 512];
__device__ __half g_ph[P_ * 512];      // p  (fp16, k-permuted)
__device__ __half g_eh[E_ * 512];      // e
__device__ __half g_pph[P_ * 512];     // pp (fp16, k-permuted)
__device__ __half g_eeh[E_ * 512];     // ee (fp16, k-permuted, +l1_b)
// l2_w frag-major tiled for 64-n tiles: [nt(8)][chunk(16)][4096B]
__device__ __half g_wth[512 * 512];

// ---------------- helpers ----------------
__device__ __forceinline__ uint32_t smem_u32(const void* p) {
    uint32_t a;
    asm("{ .reg .u64 t; cvta.to.shared.u64 t, %1; cvt.u32.u64 %0, t; }" : "=r"(a) : "l"(p));
    return a;
}
__device__ __forceinline__ void mma16(float* d, const uint32_t* a, uint32_t b0, uint32_t b1) {
    asm volatile(
        "mma.sync.aligned.m16n8k16.row.col.f32.f16.f16.f32 "
        "{%0,%1,%2,%3}, {%4,%5,%6,%7}, {%8,%9}, {%0,%1,%2,%3};"
        : "+f"(d[0]), "+f"(d[1]), "+f"(d[2]), "+f"(d[3])
        : "r"(a[0]), "r"(a[1]), "r"(a[2]), "r"(a[3]), "r"(b0), "r"(b1));
}
// relu(x + y) in packed fp16x2
__device__ __forceinline__ uint32_t hadd2_relu(uint32_t x, uint32_t y) {
    uint32_t r;
    asm("{ .reg .b32 s; add.f16x2 s, %1, %2; max.f16x2 %0, s, %3; }"
        : "=r"(r) : "r"(x), "r"(y), "r"(0u));
    return r;
}
__device__ __forceinline__ uint32_t pack_h2(float lo, float hi) {
    __half2 h = __floats2half2_rn(lo, hi);
    return *(uint32_t*)&h;
}
__device__ __forceinline__ void cp16(uint32_t s, const void* g) {
    asm volatile("cp.async.cg.shared.global [%0], [%1], 16;" :: "r"(s), "l"(g));
}
#define CP_COMMIT() asm volatile("cp.async.commit_group;" ::: "memory")
#define CP_WAIT1()  asm volatile("cp.async.wait_group 1;" ::: "memory")
#define CP_WAIT2()  asm volatile("cp.async.wait_group 2;" ::: "memory")

__device__ __forceinline__ int kperm_src(int kp) {
    int j = kp & 15, t = j >> 2, r = j & 3;
    return (kp & ~15) + 2 * t + ((r >> 1) << 3) + (r & 1);
}

// ---------------- prep (unchanged) ----------------
__global__ __launch_bounds__(256) void prep(const float* __restrict__ post,
                                            const float* __restrict__ emoji,
                                            const float* __restrict__ k1w,
                                            const float* __restrict__ k2w,
                                            const float* __restrict__ l1w,
                                            const float* __restrict__ l2w,
                                            __half* __restrict__ post_h,
                                            __half* __restrict__ emoji_h,
                                            __half* __restrict__ k1wh,
                                            __half* __restrict__ k2wh,
                                            __half* __restrict__ l1ph,
                                            __half* __restrict__ l1eh,
                                            __half* __restrict__ wth) {
#pragma unroll
    for (int it = 0; it < 8; it++) {
        int gidx = blockIdx.x * 2048 + it * 256 + threadIdx.x;
        int u = gidx;
        if (u < 524288) {
            int m = u >> 9, ks = kperm_src(u & 511);
            post_h[u] = __float2half_rn(post[m * 512 + ks]);
            continue;
        }
        u -= 524288;
        if (u < 131072) {
            int m = u >> 9, ks = kperm_src(u & 511);
            emoji_h[u] = __float2half_rn(emoji[m * 512 + ks]);
            continue;
        }
        u -= 131072;
        if (u < 262144) {
            int n = u >> 9, ks = kperm_src(u & 511);
            k1wh[u] = __float2half_rn(k1w[ks * 512 + n]);
            continue;
        }
        u -= 262144;
        if (u < 262144) {
            int n = u >> 9, ks = kperm_src(u & 511);
            k2wh[u] = __float2half_rn(k2w[ks * 512 + n]);
            continue;
        }
        u -= 262144;
        if (u < 262144) {
            int n = u >> 9, ks = kperm_src(u & 511);
            l1ph[u] = __float2half_rn(l1w[ks * 512 + n]);
            continue;
        }
        u -= 262144;
        if (u < 262144) {
            int n = u >> 9, ks = kperm_src(u & 511);
            l1eh[u] = __float2half_rn(l1w[(512 + ks) * 512 + n]);
            continue;
        }
        u -= 262144;
        {
            int nt = u >> 15;
            int rem = u & 32767;
            int c = rem >> 11;
            int byte = (rem & 2047) * 2;
            int sub = byte >> 11;
            int tt = (byte >> 9) & 3;
            int gg = (byte >> 6) & 7;
            int y = (byte & 63) ^ (tt * 16);
            int ni = y >> 3;
            int h = (y >> 1) & 3;
            int k = c * 32 + sub * 16 + 2 * tt + ((h >> 1) << 3) + (h & 1);
            int n = nt * 64 + ni * 8 + gg;
            float v = (n < OUT_) ? l2w[k * OUT_ + n] : 0.0f;
            wth[u] = __float2half_rn(v);
        }
    }
}

// ---------------- fp16 MMA GEMM for the small chain ----------------
#define GH_BUF 12288

__global__ __launch_bounds__(256) void gemm_h(const __half* __restrict__ A0,
                                              const __half* __restrict__ B0,
                                              const float* __restrict__ bias0,
                                              __half* __restrict__ out0,
                                              const __half* __restrict__ A1,
                                              const __half* __restrict__ B1,
                                              const float* __restrict__ bias1,
                                              __half* __restrict__ out1) {
    __shared__ __align__(16) char sm[3 * GH_BUF];
    const uint32_t sbu = smem_u32(sm);

    const int tid = threadIdx.x;
    const __half* A;
    const __half* B;
    const float* bias;
    __half* out;
    int mrow0;
    if (blockIdx.y < 16) {
        A = A0; B = B0; bias = bias0; out = out0; mrow0 = blockIdx.y * 64;
    } else {
        A = A1; B = B1; bias = bias1; out = out1; mrow0 = (blockIdx.y - 16) * 64;
    }
    const int ncol0 = blockIdx.x * 64;

    const int wid = tid >> 5, lane = tid & 31;
    const int g = lane >> 2, t = lane & 3;
    const int mgrp = wid >> 1, nw = (wid & 1) * 32;

    const int srow = tid >> 2, seg = tid & 3;
    const char* a_src = (const char*)(A + (size_t)(mrow0 + srow) * 512);
    const char* b_src = (const char*)(B + (size_t)(ncol0 + srow) * 512);
    const uint32_t a_d = srow * 96u + seg * 16u;
    const uint32_t b_d = 6144u + srow * 96u + seg * 16u;

#define GH_ISSUE(c)                                             \
    do {                                                        \
        uint32_t _b = sbu + ((c) % 3) * GH_BUF;                 \
        cp16(_b + a_d, a_src + (c) * 64 + seg * 16);            \
        cp16(_b + b_d, b_src + (c) * 64 + seg * 16);            \
    } while (0)

    GH_ISSUE(0); CP_COMMIT();
    GH_ISSUE(1); CP_COMMIT();

    float acc[4][4];
#pragma unroll
    for (int ni = 0; ni < 4; ni++)
#pragma unroll
        for (int j = 0; j < 4; j++) acc[ni][j] = 0.0f;

    const int arow = mgrp * 16 + g;

#pragma unroll 1
    for (int c = 0; c < 16; ++c) {
        CP_WAIT1();
        __syncthreads();
        if (c + 2 < 16) { GH_ISSUE(c + 2); CP_COMMIT(); }
        else { CP_COMMIT(); }

        const char* ab = sm + (c % 3) * GH_BUF;
        const char* bb = ab + 6144;
#pragma unroll
        for (int sub = 0; sub < 2; ++sub) {
            const uint32_t ko = sub * 32 + t * 8;
            const uint2 alo = *(const uint2*)(ab + arow * 96 + ko);
            const uint2 ahi = *(const uint2*)(ab + (arow + 8) * 96 + ko);
            uint32_t a[4] = {alo.x, ahi.x, alo.y, ahi.y};
#pragma unroll
            for (int ni = 0; ni < 4; ++ni) {
                const uint2 bv = *(const uint2*)(bb + (nw + ni * 8 + g) * 96 + ko);
                mma16(acc[ni], a, bv.x, bv.y);
            }
        }
    }

    const int m0 = mrow0 + mgrp * 16 + g;
#pragma unroll
    for (int ni = 0; ni < 4; ++ni) {
        const int ncol = ncol0 + nw + ni * 8;
        const int off = (ncol >> 4) * 16 + 4 * t + 2 * (ni & 1);
        const float b0v = bias ? bias[ncol + 2 * t] : 0.0f;
        const float b1v = bias ? bias[ncol + 2 * t + 1] : 0.0f;
        *(uint32_t*)(out + (size_t)m0 * 512 + off) =
            pack_h2(acc[ni][0] + b0v, acc[ni][1] + b1v);
        *(uint32_t*)(out + (size_t)(m0 + 8) * 512 + off) =
            pack_h2(acc[ni][2] + b0v, acc[ni][3] + b1v);
    }
#undef GH_ISSUE
}

// ---------------- main kernel ----------------
// CTA = (4p, 64e, 64n), 256 thr = 8 warps = 2 p-pairs x 4 e-groups.
// pp/ee fp16 k-permuted; A-build = add.f16x2 + max.f16x2.
// 4-stage cp.async, 2 CTAs/SM. grid 8192: bid = pg*32 + eq*8 + nt
#define EE_BUF 4096u
#define B_BUF  4096u
#define OFF_B  (4 * EE_BUF)           // 16384
#define OFF_PP (OFF_B + 4 * B_BUF)    // 32768
#define OFF_BI (OFF_PP + 4096u)       // 36864
#define DYN_SMEM (OFF_BI + 256u)      // 37120

__global__ __launch_bounds__(256, 2) void big_kernel(const __half* __restrict__ pp,
                                                     const __half* __restrict__ ee,
                                                     const __half* __restrict__ wth,
                                                     const float* __restrict__ bias,
                                                     float* __restrict__ out) {
    extern __shared__ char dsm[];
    const uint32_t sbu = smem_u32(dsm);

    const int tid = threadIdx.x;
    const int bid = blockIdx.x;
    const int nt = bid & 7, eq = (bid >> 3) & 3, pg = bid >> 5;
    const int n0 = nt * 64, e0 = eq * 64, p0 = pg * 4;

    const int wid = tid >> 5, lane = tid & 31;
    const int g = lane >> 2, t = lane & 3;
    const int pq = wid >> 2;        // p-pair 0/1
    const int e_g = wid & 3;        // 0..3

    // ---- staging ----
    const int srow = tid >> 2;                   // 0..63
    const int seg = tid & 3;
    const char* ee_src = (const char*)(ee + (size_t)(e0 + srow) * 512);
    const char* wt_src = (const char*)(wth + (size_t)nt * 32768);
    const uint32_t ee_d = srow * 64u + (((uint32_t)seg * 16u) ^ ((uint32_t)(srow & 2) * 16u));
    const uint32_t b_d = OFF_B + (uint32_t)tid * 16u;

#define ISSUE(c)                                                        \
    do {                                                                \
        uint32_t _st = ((c) & 3);                                       \
        cp16(sbu + _st * EE_BUF + ee_d, ee_src + (c) * 64 + seg * 16);  \
        cp16(sbu + _st * B_BUF + b_d, wt_src + (c) * 4096 + tid * 16);  \
    } while (0)

    ISSUE(0); CP_COMMIT();
    ISSUE(1); CP_COMMIT();
    ISSUE(2); CP_COMMIT();

    // pp (fp16 permuted, 4 rows = 4096B) + bias
    char* pp_s = dsm + OFF_PP;
    float* bias_s = (float*)(dsm + OFF_BI);
    ((uint4*)pp_s)[tid] = ((const uint4*)(pp + (size_t)p0 * 512))[tid];
    if (tid < 64) bias_s[tid] = (n0 + tid < OUT_) ? bias[n0 + tid] : 0.0f;

    float acc[16][4];   // [p(2)][ni(8)][4]
#pragma unroll
    for (int ni = 0; ni < 16; ni++)
#pragma unroll
        for (int j = 0; j < 4; j++) acc[ni][j] = 0.0f;

    // read-side constants
    const int r0 = e_g * 16 + g;
    const uint32_t aswz = (uint32_t)(g & 2) * 16u;
    const uint32_t aoff[2] = {((uint32_t)(0 * 32 + t * 8)) ^ aswz,
                              ((uint32_t)(1 * 32 + t * 8)) ^ aswz};
    const uint32_t broff = (uint32_t)(t * 512 + g * 64);
    const uint32_t bxor = (uint32_t)(t * 16);

#pragma unroll 1
    for (int c = 0; c < 16; ++c) {
        CP_WAIT2();
        __syncthreads();
        if (c + 3 < 16) { ISSUE(c + 3); CP_COMMIT(); }
        else { CP_COMMIT(); }

        const char* eb = dsm + (c & 3) * EE_BUF;
        const char* bb = dsm + OFF_B + (c & 3) * B_BUF + broff;
        const char* ppc = pp_s + (pq * 2) * 1024 + c * 64;

#pragma unroll
        for (int sub = 0; sub < 2; ++sub) {
            const uint32_t po = (uint32_t)(sub * 32 + t * 8);
            const uint2 pv0 = *(const uint2*)(ppc + po);
            const uint2 pv1 = *(const uint2*)(ppc + 1024 + po);
            const uint2 v0 = *(const uint2*)(eb + r0 * 64 + aoff[sub]);
            const uint2 v1 = *(const uint2*)(eb + (r0 + 8) * 64 + aoff[sub]);
            uint32_t a0[4], a1[4];
            a0[0] = hadd2_relu(v0.x, pv0.x);
            a0[1] = hadd2_relu(v1.x, pv0.x);
            a0[2] = hadd2_relu(v0.y, pv0.y);
            a0[3] = hadd2_relu(v1.y, pv0.y);
            a1[0] = hadd2_relu(v0.x, pv1.x);
            a1[1] = hadd2_relu(v1.x, pv1.x);
            a1[2] = hadd2_relu(v0.y, pv1.y);
            a1[3] = hadd2_relu(v1.y, pv1.y);

            const char* bs = bb + sub * 2048;
            uint4 bq = *(const uint4*)(bs + (0u ^ bxor));
#pragma unroll
            for (int nip = 0; nip < 4; ++nip) {
                uint4 bq_n;
                if (nip < 3)
                    bq_n = *(const uint4*)(bs + (((uint32_t)(nip + 1) * 16u) ^ bxor));
                mma16(acc[2 * nip], a0, bq.x, bq.y);
                mma16(acc[2 * nip + 1], a0, bq.z, bq.w);
                mma16(acc[8 + 2 * nip], a1, bq.x, bq.y);
                mma16(acc[8 + 2 * nip + 1], a1, bq.z, bq.w);
                if (nip < 3) bq = bq_n;
            }
        }
    }

    // ---- epilogue ----
    const int er0 = e0 + e_g * 16 + g;
#pragma unroll
    for (int pq2 = 0; pq2 < 2; ++pq2) {
        const size_t prow = (size_t)(p0 + pq * 2 + pq2) * E_;
        float* o0 = out + (prow + er0) * OUT_;
        float* o1 = out + (prow + er0 + 8) * OUT_;
#pragma unroll
        for (int ni = 0; ni < 8; ++ni) {
            const int ncl = ni * 8 + 2 * t;
            const int n = n0 + ncl;
            if (n < OUT_) {
                const float bz0 = bias_s[ncl], bz1 = bias_s[ncl + 1];
                const float* av = acc[pq2 * 8 + ni];
                float2 w0, w1;
                w0.x = fmaxf(av[0] + bz0, 0.0f);
                w0.y = fmaxf(av[1] + bz1, 0.0f);
                w1.x = fmaxf(av[2] + bz0, 0.0f);
                w1.y = fmaxf(av[3] + bz1, 0.0f);
                *(float2*)(o0 + n) = w0;
                *(float2*)(o1 + n) = w1;
            }
        }
    }
#undef ISSUE
}

// ---------------- launch ----------------
extern "C" void kernel_launch(void* const* d_in, const int* in_sizes, int n_in,
                              void* d_out, int out_size) {
    const float* post  = (const float*)d_in[0];
    const float* emoji = (const float*)d_in[1];
    const float* k1_w  = (const float*)d_in[2];
    const float* k1_b  = (const float*)d_in[3];
    const float* k2_w  = (const float*)d_in[4];
    const float* k2_b  = (const float*)d_in[5];
    const float* l1_w  = (const float*)d_in[6];
    const float* l1_b  = (const float*)d_in[7];
    const float* l2_w  = (const float*)d_in[8];
    const float* l2_b  = (const float*)d_in[9];
    float* out = (float*)d_out;

    __half *pPH, *pEH, *pK1, *pK2, *pL1P, *pL1E, *pPh, *pEh, *pPPH, *pEEH, *pWT;
    cudaGetSymbolAddress((void**)&pPH, g_posth);
    cudaGetSymbolAddress((void**)&pEH, g_emojih);
    cudaGetSymbolAddress((void**)&pK1, g_k1wh);
    cudaGetSymbolAddress((void**)&pK2, g_k2wh);
    cudaGetSymbolAddress((void**)&pL1P, g_l1ph);
    cudaGetSymbolAddress((void**)&pL1E, g_l1eh);
    cudaGetSymbolAddress((void**)&pPh, g_ph);
    cudaGetSymbolAddress((void**)&pEh, g_eh);
    cudaGetSymbolAddress((void**)&pPPH, g_pph);
    cudaGetSymbolAddress((void**)&pEEH, g_eeh);
    cudaGetSymbolAddress((void**)&pWT, g_wth);

    cudaFuncSetAttribute(big_kernel, cudaFuncAttributeMaxDynamicSharedMemorySize,
                         DYN_SMEM);

    prep<<<960, 256>>>(post, emoji, k1_w, k2_w, l1_w, l2_w,
                       pPH, pEH, pK1, pK2, pL1P, pL1E, pWT);
    gemm_h<<<dim3(8, 20), 256>>>(pPH, pK1, k1_b, pPh,
                                 pEH, pK2, k2_b, pEh);
    gemm_h<<<dim3(8, 20), 256>>>(pPh, pL1P, nullptr, pPPH,
                                 pEh, pL1E, l1_b, pEEH);
    big_kernel<<<8192, 256, DYN_SMEM>>>(pPPH, pEEH, pWT, l2_b, out);
}

// round 11
// speedup vs baseline: 1.5482x; 1.5482x over previous
#include <cuda_runtime.h>
#include <cuda_fp16.h>
#include <cstdint>

#define D_ 512
#define P_ 1024
#define E_ 256
#define OUT_ 500

// ---------------- device scratch ----------------
__device__ __half g_posth[P_ * D_];
__device__ __half g_emojih[E_ * D_];
__device__ __half g_k1wh[512 * 512];
__device__ __half g_k2wh[512 * 512];
__device__ __half g_l1ph[512 * 512];
__device__ __half g_l1eh[512 * 512];
__device__ __half g_ph[P_ * 512];      // p  (fp16, k-permuted)
__device__ __half g_eh[E_ * 512];      // e
__device__ __half g_pph[P_ * 512];     // pp (fp16, k-permuted)
__device__ __half g_eeh[E_ * 512];     // ee (fp16, k-permuted, +l1_b)
// l2_w frag-major tiled for 64-n tiles: [nt(8)][chunk(16)][4096B]
__device__ __half g_wth[512 * 512];

// ---------------- helpers ----------------
__device__ __forceinline__ uint32_t smem_u32(const void* p) {
    uint32_t a;
    asm("{ .reg .u64 t; cvta.to.shared.u64 t, %1; cvt.u32.u64 %0, t; }" : "=r"(a) : "l"(p));
    return a;
}
__device__ __forceinline__ void mma16(float* d, const uint32_t* a, uint32_t b0, uint32_t b1) {
    asm volatile(
        "mma.sync.aligned.m16n8k16.row.col.f32.f16.f16.f32 "
        "{%0,%1,%2,%3}, {%4,%5,%6,%7}, {%8,%9}, {%0,%1,%2,%3};"
        : "+f"(d[0]), "+f"(d[1]), "+f"(d[2]), "+f"(d[3])
        : "r"(a[0]), "r"(a[1]), "r"(a[2]), "r"(a[3]), "r"(b0), "r"(b1));
}
// relu(x + y) in packed fp16x2
__device__ __forceinline__ uint32_t hadd2_relu(uint32_t x, uint32_t y) {
    uint32_t r;
    asm("{ .reg .b32 s; add.f16x2 s, %1, %2; max.f16x2 %0, s, %3; }"
        : "=r"(r) : "r"(x), "r"(y), "r"(0u));
    return r;
}
__device__ __forceinline__ uint32_t pack_h2(float lo, float hi) {
    __half2 h = __floats2half2_rn(lo, hi);
    return *(uint32_t*)&h;
}
__device__ __forceinline__ void cp16(uint32_t s, const void* g) {
    asm volatile("cp.async.cg.shared.global [%0], [%1], 16;" :: "r"(s), "l"(g));
}
#define CP_COMMIT() asm volatile("cp.async.commit_group;" ::: "memory")
#define CP_WAIT1()  asm volatile("cp.async.wait_group 1;" ::: "memory")
#define CP_WAIT2()  asm volatile("cp.async.wait_group 2;" ::: "memory")

__device__ __forceinline__ int kperm_src(int kp) {
    int j = kp & 15, t = j >> 2, r = j & 3;
    return (kp & ~15) + 2 * t + ((r >> 1) << 3) + (r & 1);
}

// ---------------- prep (unchanged) ----------------
__global__ __launch_bounds__(256) void prep(const float* __restrict__ post,
                                            const float* __restrict__ emoji,
                                            const float* __restrict__ k1w,
                                            const float* __restrict__ k2w,
                                            const float* __restrict__ l1w,
                                            const float* __restrict__ l2w,
                                            __half* __restrict__ post_h,
                                            __half* __restrict__ emoji_h,
                                            __half* __restrict__ k1wh,
                                            __half* __restrict__ k2wh,
                                            __half* __restrict__ l1ph,
                                            __half* __restrict__ l1eh,
                                            __half* __restrict__ wth) {
#pragma unroll
    for (int it = 0; it < 8; it++) {
        int gidx = blockIdx.x * 2048 + it * 256 + threadIdx.x;
        int u = gidx;
        if (u < 524288) {
            int m = u >> 9, ks = kperm_src(u & 511);
            post_h[u] = __float2half_rn(post[m * 512 + ks]);
            continue;
        }
        u -= 524288;
        if (u < 131072) {
            int m = u >> 9, ks = kperm_src(u & 511);
            emoji_h[u] = __float2half_rn(emoji[m * 512 + ks]);
            continue;
        }
        u -= 131072;
        if (u < 262144) {
            int n = u >> 9, ks = kperm_src(u & 511);
            k1wh[u] = __float2half_rn(k1w[ks * 512 + n]);
            continue;
        }
        u -= 262144;
        if (u < 262144) {
            int n = u >> 9, ks = kperm_src(u & 511);
            k2wh[u] = __float2half_rn(k2w[ks * 512 + n]);
            continue;
        }
        u -= 262144;
        if (u < 262144) {
            int n = u >> 9, ks = kperm_src(u & 511);
            l1ph[u] = __float2half_rn(l1w[ks * 512 + n]);
            continue;
        }
        u -= 262144;
        if (u < 262144) {
            int n = u >> 9, ks = kperm_src(u & 511);
            l1eh[u] = __float2half_rn(l1w[(512 + ks) * 512 + n]);
            continue;
        }
        u -= 262144;
        {
            int nt = u >> 15;
            int rem = u & 32767;
            int c = rem >> 11;
            int byte = (rem & 2047) * 2;
            int sub = byte >> 11;
            int tt = (byte >> 9) & 3;
            int gg = (byte >> 6) & 7;
            int y = (byte & 63) ^ (tt * 16);
            int ni = y >> 3;
            int h = (y >> 1) & 3;
            int k = c * 32 + sub * 16 + 2 * tt + ((h >> 1) << 3) + (h & 1);
            int n = nt * 64 + ni * 8 + gg;
            float v = (n < OUT_) ? l2w[k * OUT_ + n] : 0.0f;
            wth[u] = __float2half_rn(v);
        }
    }
}

// ---------------- fp16 MMA GEMM for the small chain (unchanged) ----------------
#define GH_BUF 12288

__global__ __launch_bounds__(256) void gemm_h(const __half* __restrict__ A0,
                                              const __half* __restrict__ B0,
                                              const float* __restrict__ bias0,
                                              __half* __restrict__ out0,
                                              const __half* __restrict__ A1,
                                              const __half* __restrict__ B1,
                                              const float* __restrict__ bias1,
                                              __half* __restrict__ out1) {
    __shared__ __align__(16) char sm[3 * GH_BUF];
    const uint32_t sbu = smem_u32(sm);

    const int tid = threadIdx.x;
    const __half* A;
    const __half* B;
    const float* bias;
    __half* out;
    int mrow0;
    if (blockIdx.y < 16) {
        A = A0; B = B0; bias = bias0; out = out0; mrow0 = blockIdx.y * 64;
    } else {
        A = A1; B = B1; bias = bias1; out = out1; mrow0 = (blockIdx.y - 16) * 64;
    }
    const int ncol0 = blockIdx.x * 64;

    const int wid = tid >> 5, lane = tid & 31;
    const int g = lane >> 2, t = lane & 3;
    const int mgrp = wid >> 1, nw = (wid & 1) * 32;

    const int srow = tid >> 2, seg = tid & 3;
    const char* a_src = (const char*)(A + (size_t)(mrow0 + srow) * 512);
    const char* b_src = (const char*)(B + (size_t)(ncol0 + srow) * 512);
    const uint32_t a_d = srow * 96u + seg * 16u;
    const uint32_t b_d = 6144u + srow * 96u + seg * 16u;

#define GH_ISSUE(c)                                             \
    do {                                                        \
        uint32_t _b = sbu + ((c) % 3) * GH_BUF;                 \
        cp16(_b + a_d, a_src + (c) * 64 + seg * 16);            \
        cp16(_b + b_d, b_src + (c) * 64 + seg * 16);            \
    } while (0)

    GH_ISSUE(0); CP_COMMIT();
    GH_ISSUE(1); CP_COMMIT();

    float acc[4][4];
#pragma unroll
    for (int ni = 0; ni < 4; ni++)
#pragma unroll
        for (int j = 0; j < 4; j++) acc[ni][j] = 0.0f;

    const int arow = mgrp * 16 + g;

#pragma unroll 1
    for (int c = 0; c < 16; ++c) {
        CP_WAIT1();
        __syncthreads();
        if (c + 2 < 16) { GH_ISSUE(c + 2); CP_COMMIT(); }
        else { CP_COMMIT(); }

        const char* ab = sm + (c % 3) * GH_BUF;
        const char* bb = ab + 6144;
#pragma unroll
        for (int sub = 0; sub < 2; ++sub) {
            const uint32_t ko = sub * 32 + t * 8;
            const uint2 alo = *(const uint2*)(ab + arow * 96 + ko);
            const uint2 ahi = *(const uint2*)(ab + (arow + 8) * 96 + ko);
            uint32_t a[4] = {alo.x, ahi.x, alo.y, ahi.y};
#pragma unroll
            for (int ni = 0; ni < 4; ++ni) {
                const uint2 bv = *(const uint2*)(bb + (nw + ni * 8 + g) * 96 + ko);
                mma16(acc[ni], a, bv.x, bv.y);
            }
        }
    }

    const int m0 = mrow0 + mgrp * 16 + g;
#pragma unroll
    for (int ni = 0; ni < 4; ++ni) {
        const int ncol = ncol0 + nw + ni * 8;
        const int off = (ncol >> 4) * 16 + 4 * t + 2 * (ni & 1);
        const float b0v = bias ? bias[ncol + 2 * t] : 0.0f;
        const float b1v = bias ? bias[ncol + 2 * t + 1] : 0.0f;
        *(uint32_t*)(out + (size_t)m0 * 512 + off) =
            pack_h2(acc[ni][0] + b0v, acc[ni][1] + b1v);
        *(uint32_t*)(out + (size_t)(m0 + 8) * 512 + off) =
            pack_h2(acc[ni][2] + b0v, acc[ni][3] + b1v);
    }
#undef GH_ISSUE
}

// ---------------- main kernel ----------------
// CTA = (4p, 64e, 64n), 256 thr = 8 warps = 2 p-pairs x 4 e-groups.
// ee fp16 in 128B-stride rows (64B data + pad), XOR X(r)=((r&1)*64)^((r&2)*16)
// -> conflict-free LDS.64 reads and cp.async writes. A-build = f16x2.
// 4-stage cp.async, 2 CTAs/SM. grid 8192: bid = pg*32 + eq*8 + nt
#define EE_BUF 8192u
#define B_BUF  4096u
#define OFF_B  (4 * EE_BUF)           // 32768
#define OFF_PP (OFF_B + 4 * B_BUF)    // 49152
#define OFF_BI (OFF_PP + 4096u)       // 53248
#define DYN_SMEM (OFF_BI + 256u)      // 53504

__global__ __launch_bounds__(256, 2) void big_kernel(const __half* __restrict__ pp,
                                                     const __half* __restrict__ ee,
                                                     const __half* __restrict__ wth,
                                                     const float* __restrict__ bias,
                                                     float* __restrict__ out) {
    extern __shared__ char dsm[];
    const uint32_t sbu = smem_u32(dsm);

    const int tid = threadIdx.x;
    const int bid = blockIdx.x;
    const int nt = bid & 7, eq = (bid >> 3) & 3, pg = bid >> 5;
    const int n0 = nt * 64, e0 = eq * 64, p0 = pg * 4;

    const int wid = tid >> 5, lane = tid & 31;
    const int g = lane >> 2, t = lane & 3;
    const int pq = wid >> 2;        // p-pair 0/1
    const int e_g = wid & 3;        // 0..3

    // ---- staging ----
    const int srow = tid >> 2;                   // 0..63
    const int seg = tid & 3;
    const char* ee_src = (const char*)(ee + (size_t)(e0 + srow) * 512);
    const char* wt_src = (const char*)(wth + (size_t)nt * 32768);
    const uint32_t exw = (((uint32_t)(srow & 1)) * 64u) ^ (((uint32_t)(srow & 2)) * 16u);
    const uint32_t ee_d = srow * 128u + (((uint32_t)seg * 16u) ^ exw);
    const uint32_t b_d = OFF_B + (uint32_t)tid * 16u;

#define ISSUE(c)                                                        \
    do {                                                                \
        uint32_t _st = ((c) & 3);                                       \
        cp16(sbu + _st * EE_BUF + ee_d, ee_src + (c) * 64 + seg * 16);  \
        cp16(sbu + _st * B_BUF + b_d, wt_src + (c) * 4096 + tid * 16);  \
    } while (0)

    ISSUE(0); CP_COMMIT();
    ISSUE(1); CP_COMMIT();
    ISSUE(2); CP_COMMIT();

    // pp (fp16 permuted, 4 rows = 4096B) + bias
    char* pp_s = dsm + OFF_PP;
    float* bias_s = (float*)(dsm + OFF_BI);
    ((uint4*)pp_s)[tid] = ((const uint4*)(pp + (size_t)p0 * 512))[tid];
    if (tid < 64) bias_s[tid] = (n0 + tid < OUT_) ? bias[n0 + tid] : 0.0f;

    float acc[16][4];   // [p(2)][ni(8)][4]
#pragma unroll
    for (int ni = 0; ni < 16; ni++)
#pragma unroll
        for (int j = 0; j < 4; j++) acc[ni][j] = 0.0f;

    // read-side constants
    const int r0 = e_g * 16 + g;
    const uint32_t axor = (((uint32_t)(g & 1)) * 64u) ^ (((uint32_t)(g & 2)) * 16u);
    const uint32_t aoff[2] = {((uint32_t)(0 * 32 + t * 8)) ^ axor,
                              ((uint32_t)(1 * 32 + t * 8)) ^ axor};
    const uint32_t broff = (uint32_t)(t * 512 + g * 64);
    const uint32_t bxor = (uint32_t)(t * 16);

#pragma unroll 1
    for (int c = 0; c < 16; ++c) {
        CP_WAIT2();
        __syncthreads();
        if (c + 3 < 16) { ISSUE(c + 3); CP_COMMIT(); }
        else { CP_COMMIT(); }

        const char* eb = dsm + (c & 3) * EE_BUF;
        const char* bb = dsm + OFF_B + (c & 3) * B_BUF + broff;
        const char* ppc = pp_s + (pq * 2) * 1024 + c * 64;

#pragma unroll
        for (int sub = 0; sub < 2; ++sub) {
            const uint32_t po = (uint32_t)(sub * 32 + t * 8);
            const uint2 pv0 = *(const uint2*)(ppc + po);
            const uint2 pv1 = *(const uint2*)(ppc + 1024 + po);
            const uint2 v0 = *(const uint2*)(eb + r0 * 128 + aoff[sub]);
            const uint2 v1 = *(const uint2*)(eb + (r0 + 8) * 128 + aoff[sub]);
            uint32_t a0[4], a1[4];
            a0[0] = hadd2_relu(v0.x, pv0.x);
            a0[1] = hadd2_relu(v1.x, pv0.x);
            a0[2] = hadd2_relu(v0.y, pv0.y);
            a0[3] = hadd2_relu(v1.y, pv0.y);
            a1[0] = hadd2_relu(v0.x, pv1.x);
            a1[1] = hadd2_relu(v1.x, pv1.x);
            a1[2] = hadd2_relu(v0.y, pv1.y);
            a1[3] = hadd2_relu(v1.y, pv1.y);

            const char* bs = bb + sub * 2048;
            uint4 bq = *(const uint4*)(bs + (0u ^ bxor));
#pragma unroll
            for (int nip = 0; nip < 4; ++nip) {
                uint4 bq_n;
                if (nip < 3)
                    bq_n = *(const uint4*)(bs + (((uint32_t)(nip + 1) * 16u) ^ bxor));
                mma16(acc[2 * nip], a0, bq.x, bq.y);
                mma16(acc[2 * nip + 1], a0, bq.z, bq.w);
                mma16(acc[8 + 2 * nip], a1, bq.x, bq.y);
                mma16(acc[8 + 2 * nip + 1], a1, bq.z, bq.w);
                if (nip < 3) bq = bq_n;
            }
        }
    }

    // ---- epilogue ----
    const int er0 = e0 + e_g * 16 + g;
#pragma unroll
    for (int pq2 = 0; pq2 < 2; ++pq2) {
        const size_t prow = (size_t)(p0 + pq * 2 + pq2) * E_;
        float* o0 = out + (prow + er0) * OUT_;
        float* o1 = out + (prow + er0 + 8) * OUT_;
#pragma unroll
        for (int ni = 0; ni < 8; ++ni) {
            const int ncl = ni * 8 + 2 * t;
            const int n = n0 + ncl;
            if (n < OUT_) {
                const float bz0 = bias_s[ncl], bz1 = bias_s[ncl + 1];
                const float* av = acc[pq2 * 8 + ni];
                float2 w0, w1;
                w0.x = fmaxf(av[0] + bz0, 0.0f);
                w0.y = fmaxf(av[1] + bz1, 0.0f);
                w1.x = fmaxf(av[2] + bz0, 0.0f);
                w1.y = fmaxf(av[3] + bz1, 0.0f);
                *(float2*)(o0 + n) = w0;
                *(float2*)(o1 + n) = w1;
            }
        }
    }
#undef ISSUE
}

// ---------------- launch ----------------
extern "C" void kernel_launch(void* const* d_in, const int* in_sizes, int n_in,
                              void* d_out, int out_size) {
    const float* post  = (const float*)d_in[0];
    const float* emoji = (const float*)d_in[1];
    const float* k1_w  = (const float*)d_in[2];
    const float* k1_b  = (const float*)d_in[3];
    const float* k2_w  = (const float*)d_in[4];
    const float* k2_b  = (const float*)d_in[5];
    const float* l1_w  = (const float*)d_in[6];
    const float* l1_b  = (const float*)d_in[7];
    const float* l2_w  = (const float*)d_in[8];
    const float* l2_b  = (const float*)d_in[9];
    float* out = (float*)d_out;

    __half *pPH, *pEH, *pK1, *pK2, *pL1P, *pL1E, *pPh, *pEh, *pPPH, *pEEH, *pWT;
    cudaGetSymbolAddress((void**)&pPH, g_posth);
    cudaGetSymbolAddress((void**)&pEH, g_emojih);
    cudaGetSymbolAddress((void**)&pK1, g_k1wh);
    cudaGetSymbolAddress((void**)&pK2, g_k2wh);
    cudaGetSymbolAddress((void**)&pL1P, g_l1ph);
    cudaGetSymbolAddress((void**)&pL1E, g_l1eh);
    cudaGetSymbolAddress((void**)&pPh, g_ph);
    cudaGetSymbolAddress((void**)&pEh, g_eh);
    cudaGetSymbolAddress((void**)&pPPH, g_pph);
    cudaGetSymbolAddress((void**)&pEEH, g_eeh);
    cudaGetSymbolAddress((void**)&pWT, g_wth);

    cudaFuncSetAttribute(big_kernel, cudaFuncAttributeMaxDynamicSharedMemorySize,
                         DYN_SMEM);

    prep<<<960, 256>>>(post, emoji, k1_w, k2_w, l1_w, l2_w,
                       pPH, pEH, pK1, pK2, pL1P, pL1E, pWT);
    gemm_h<<<dim3(8, 20), 256>>>(pPH, pK1, k1_b, pPh,
                                 pEH, pK2, k2_b, pEh);
    gemm_h<<<dim3(8, 20), 256>>>(pPh, pL1P, nullptr, pPPH,
                                 pEh, pL1E, l1_b, pEEH);
    big_kernel<<<8192, 256, DYN_SMEM>>>(pPPH, pEEH, pWT, l2_b, out);
}

// round 12
// speedup vs baseline: 1.5534x; 1.0034x over previous
#include <cuda_runtime.h>
#include <cuda_fp16.h>
#include <cstdint>

#define D_ 512
#define P_ 1024
#define E_ 256
#define OUT_ 500

// ---------------- device scratch ----------------
__device__ __half g_posth[P_ * D_];
__device__ __half g_emojih[E_ * D_];
__device__ __half g_k1wh[512 * 512];
__device__ __half g_k2wh[512 * 512];
__device__ __half g_l1ph[512 * 512];
__device__ __half g_l1eh[512 * 512];
__device__ __half g_ph[P_ * 512];      // p  (fp16, k-permuted)
__device__ __half g_eh[E_ * 512];      // e
__device__ __half g_pph[P_ * 512];     // pp (fp16, k-permuted)
__device__ __half g_eeh[E_ * 512];     // ee (fp16, k-permuted, +l1_b)
// l2_w frag-major tiled for 64-n tiles: [nt(8)][chunk(16)][4096B]
__device__ __half g_wth[512 * 512];

// ---------------- helpers ----------------
__device__ __forceinline__ uint32_t smem_u32(const void* p) {
    uint32_t a;
    asm("{ .reg .u64 t; cvta.to.shared.u64 t, %1; cvt.u32.u64 %0, t; }" : "=r"(a) : "l"(p));
    return a;
}
__device__ __forceinline__ void mma16(float* d, const uint32_t* a, uint32_t b0, uint32_t b1) {
    asm volatile(
        "mma.sync.aligned.m16n8k16.row.col.f32.f16.f16.f32 "
        "{%0,%1,%2,%3}, {%4,%5,%6,%7}, {%8,%9}, {%0,%1,%2,%3};"
        : "+f"(d[0]), "+f"(d[1]), "+f"(d[2]), "+f"(d[3])
        : "r"(a[0]), "r"(a[1]), "r"(a[2]), "r"(a[3]), "r"(b0), "r"(b1));
}
// relu(x + y) in packed fp16x2
__device__ __forceinline__ uint32_t hadd2_relu(uint32_t x, uint32_t y) {
    uint32_t r;
    asm("{ .reg .b32 s; add.f16x2 s, %1, %2; max.f16x2 %0, s, %3; }"
        : "=r"(r) : "r"(x), "r"(y), "r"(0u));
    return r;
}
__device__ __forceinline__ uint32_t pack_h2(float lo, float hi) {
    __half2 h = __floats2half2_rn(lo, hi);
    return *(uint32_t*)&h;
}
__device__ __forceinline__ void cp16(uint32_t s, const void* g) {
    asm volatile("cp.async.cg.shared.global [%0], [%1], 16;" :: "r"(s), "l"(g));
}
#define CP_COMMIT() asm volatile("cp.async.commit_group;" ::: "memory")
#define CP_WAIT1()  asm volatile("cp.async.wait_group 1;" ::: "memory")
#define CP_WAIT2()  asm volatile("cp.async.wait_group 2;" ::: "memory")

__device__ __forceinline__ int kperm_src(int kp) {
    int j = kp & 15, t = j >> 2, r = j & 3;
    return (kp & ~15) + 2 * t + ((r >> 1) << 3) + (r & 1);
}

// ---------------- prep (unchanged) ----------------
__global__ __launch_bounds__(256) void prep(const float* __restrict__ post,
                                            const float* __restrict__ emoji,
                                            const float* __restrict__ k1w,
                                            const float* __restrict__ k2w,
                                            const float* __restrict__ l1w,
                                            const float* __restrict__ l2w,
                                            __half* __restrict__ post_h,
                                            __half* __restrict__ emoji_h,
                                            __half* __restrict__ k1wh,
                                            __half* __restrict__ k2wh,
                                            __half* __restrict__ l1ph,
                                            __half* __restrict__ l1eh,
                                            __half* __restrict__ wth) {
#pragma unroll
    for (int it = 0; it < 8; it++) {
        int gidx = blockIdx.x * 2048 + it * 256 + threadIdx.x;
        int u = gidx;
        if (u < 524288) {
            int m = u >> 9, ks = kperm_src(u & 511);
            post_h[u] = __float2half_rn(post[m * 512 + ks]);
            continue;
        }
        u -= 524288;
        if (u < 131072) {
            int m = u >> 9, ks = kperm_src(u & 511);
            emoji_h[u] = __float2half_rn(emoji[m * 512 + ks]);
            continue;
        }
        u -= 131072;
        if (u < 262144) {
            int n = u >> 9, ks = kperm_src(u & 511);
            k1wh[u] = __float2half_rn(k1w[ks * 512 + n]);
            continue;
        }
        u -= 262144;
        if (u < 262144) {
            int n = u >> 9, ks = kperm_src(u & 511);
            k2wh[u] = __float2half_rn(k2w[ks * 512 + n]);
            continue;
        }
        u -= 262144;
        if (u < 262144) {
            int n = u >> 9, ks = kperm_src(u & 511);
            l1ph[u] = __float2half_rn(l1w[ks * 512 + n]);
            continue;
        }
        u -= 262144;
        if (u < 262144) {
            int n = u >> 9, ks = kperm_src(u & 511);
            l1eh[u] = __float2half_rn(l1w[(512 + ks) * 512 + n]);
            continue;
        }
        u -= 262144;
        {
            int nt = u >> 15;
            int rem = u & 32767;
            int c = rem >> 11;
            int byte = (rem & 2047) * 2;
            int sub = byte >> 11;
            int tt = (byte >> 9) & 3;
            int gg = (byte >> 6) & 7;
            int y = (byte & 63) ^ (tt * 16);
            int ni = y >> 3;
            int h = (y >> 1) & 3;
            int k = c * 32 + sub * 16 + 2 * tt + ((h >> 1) << 3) + (h & 1);
            int n = nt * 64 + ni * 8 + gg;
            float v = (n < OUT_) ? l2w[k * OUT_ + n] : 0.0f;
            wth[u] = __float2half_rn(v);
        }
    }
}

// ---------------- fp16 MMA GEMM for the small chain (unchanged) ----------------
#define GH_BUF 12288

__global__ __launch_bounds__(256) void gemm_h(const __half* __restrict__ A0,
                                              const __half* __restrict__ B0,
                                              const float* __restrict__ bias0,
                                              __half* __restrict__ out0,
                                              const __half* __restrict__ A1,
                                              const __half* __restrict__ B1,
                                              const float* __restrict__ bias1,
                                              __half* __restrict__ out1) {
    __shared__ __align__(16) char sm[3 * GH_BUF];
    const uint32_t sbu = smem_u32(sm);

    const int tid = threadIdx.x;
    const __half* A;
    const __half* B;
    const float* bias;
    __half* out;
    int mrow0;
    if (blockIdx.y < 16) {
        A = A0; B = B0; bias = bias0; out = out0; mrow0 = blockIdx.y * 64;
    } else {
        A = A1; B = B1; bias = bias1; out = out1; mrow0 = (blockIdx.y - 16) * 64;
    }
    const int ncol0 = blockIdx.x * 64;

    const int wid = tid >> 5, lane = tid & 31;
    const int g = lane >> 2, t = lane & 3;
    const int mgrp = wid >> 1, nw = (wid & 1) * 32;

    const int srow = tid >> 2, seg = tid & 3;
    const char* a_src = (const char*)(A + (size_t)(mrow0 + srow) * 512);
    const char* b_src = (const char*)(B + (size_t)(ncol0 + srow) * 512);
    const uint32_t a_d = srow * 96u + seg * 16u;
    const uint32_t b_d = 6144u + srow * 96u + seg * 16u;

#define GH_ISSUE(c)                                             \
    do {                                                        \
        uint32_t _b = sbu + ((c) % 3) * GH_BUF;                 \
        cp16(_b + a_d, a_src + (c) * 64 + seg * 16);            \
        cp16(_b + b_d, b_src + (c) * 64 + seg * 16);            \
    } while (0)

    GH_ISSUE(0); CP_COMMIT();
    GH_ISSUE(1); CP_COMMIT();

    float acc[4][4];
#pragma unroll
    for (int ni = 0; ni < 4; ni++)
#pragma unroll
        for (int j = 0; j < 4; j++) acc[ni][j] = 0.0f;

    const int arow = mgrp * 16 + g;

#pragma unroll 1
    for (int c = 0; c < 16; ++c) {
        CP_WAIT1();
        __syncthreads();
        if (c + 2 < 16) { GH_ISSUE(c + 2); CP_COMMIT(); }
        else { CP_COMMIT(); }

        const char* ab = sm + (c % 3) * GH_BUF;
        const char* bb = ab + 6144;
#pragma unroll
        for (int sub = 0; sub < 2; ++sub) {
            const uint32_t ko = sub * 32 + t * 8;
            const uint2 alo = *(const uint2*)(ab + arow * 96 + ko);
            const uint2 ahi = *(const uint2*)(ab + (arow + 8) * 96 + ko);
            uint32_t a[4] = {alo.x, ahi.x, alo.y, ahi.y};
#pragma unroll
            for (int ni = 0; ni < 4; ++ni) {
                const uint2 bv = *(const uint2*)(bb + (nw + ni * 8 + g) * 96 + ko);
                mma16(acc[ni], a, bv.x, bv.y);
            }
        }
    }

    const int m0 = mrow0 + mgrp * 16 + g;
#pragma unroll
    for (int ni = 0; ni < 4; ++ni) {
        const int ncol = ncol0 + nw + ni * 8;
        const int off = (ncol >> 4) * 16 + 4 * t + 2 * (ni & 1);
        const float b0v = bias ? bias[ncol + 2 * t] : 0.0f;
        const float b1v = bias ? bias[ncol + 2 * t + 1] : 0.0f;
        *(uint32_t*)(out + (size_t)m0 * 512 + off) =
            pack_h2(acc[ni][0] + b0v, acc[ni][1] + b1v);
        *(uint32_t*)(out + (size_t)(m0 + 8) * 512 + off) =
            pack_h2(acc[ni][2] + b0v, acc[ni][3] + b1v);
    }
#undef GH_ISSUE
}

// ---------------- main kernel ----------------
// CTA = (4p, 64e, 64n), 256 thr = 8 warps = 2 p-pairs x 4 e-groups.
// Whole-chunk operand batching: all ee/pp LDS + all 16 A-builds at chunk top,
// then 32 MMAs back-to-back with B quads prefetched 1 ahead.
#define EE_BUF 8192u
#define B_BUF  4096u
#define OFF_B  (4 * EE_BUF)           // 32768
#define OFF_PP (OFF_B + 4 * B_BUF)    // 49152
#define OFF_BI (OFF_PP + 4096u)       // 53248
#define DYN_SMEM (OFF_BI + 256u)      // 53504

__global__ __launch_bounds__(256, 2) void big_kernel(const __half* __restrict__ pp,
                                                     const __half* __restrict__ ee,
                                                     const __half* __restrict__ wth,
                                                     const float* __restrict__ bias,
                                                     float* __restrict__ out) {
    extern __shared__ char dsm[];
    const uint32_t sbu = smem_u32(dsm);

    const int tid = threadIdx.x;
    const int bid = blockIdx.x;
    const int nt = bid & 7, eq = (bid >> 3) & 3, pg = bid >> 5;
    const int n0 = nt * 64, e0 = eq * 64, p0 = pg * 4;

    const int wid = tid >> 5, lane = tid & 31;
    const int g = lane >> 2, t = lane & 3;
    const int pq = wid >> 2;        // p-pair 0/1
    const int e_g = wid & 3;        // 0..3

    // ---- staging ----
    const int srow = tid >> 2;                   // 0..63
    const int seg = tid & 3;
    const char* ee_src = (const char*)(ee + (size_t)(e0 + srow) * 512);
    const char* wt_src = (const char*)(wth + (size_t)nt * 32768);
    const uint32_t exw = (((uint32_t)(srow & 1)) * 64u) ^ (((uint32_t)(srow & 2)) * 16u);
    const uint32_t ee_d = srow * 128u + (((uint32_t)seg * 16u) ^ exw);
    const uint32_t b_d = OFF_B + (uint32_t)tid * 16u;

#define ISSUE(c)                                                        \
    do {                                                                \
        uint32_t _st = ((c) & 3);                                       \
        cp16(sbu + _st * EE_BUF + ee_d, ee_src + (c) * 64 + seg * 16);  \
        cp16(sbu + _st * B_BUF + b_d, wt_src + (c) * 4096 + tid * 16);  \
    } while (0)

    ISSUE(0); CP_COMMIT();
    ISSUE(1); CP_COMMIT();
    ISSUE(2); CP_COMMIT();

    // pp (fp16 permuted, 4 rows = 4096B) + bias
    char* pp_s = dsm + OFF_PP;
    float* bias_s = (float*)(dsm + OFF_BI);
    ((uint4*)pp_s)[tid] = ((const uint4*)(pp + (size_t)p0 * 512))[tid];
    if (tid < 64) bias_s[tid] = (n0 + tid < OUT_) ? bias[n0 + tid] : 0.0f;

    float acc[16][4];   // [p(2)][ni(8)][4]
#pragma unroll
    for (int ni = 0; ni < 16; ni++)
#pragma unroll
        for (int j = 0; j < 4; j++) acc[ni][j] = 0.0f;

    // read-side constants
    const int r0 = e_g * 16 + g;
    const uint32_t axor = (((uint32_t)(g & 1)) * 64u) ^ (((uint32_t)(g & 2)) * 16u);
    const uint32_t aoff[2] = {((uint32_t)(0 * 32 + t * 8)) ^ axor,
                              ((uint32_t)(1 * 32 + t * 8)) ^ axor};
    const uint32_t broff = (uint32_t)(t * 512 + g * 64);
    const uint32_t bxor = (uint32_t)(t * 16);

#pragma unroll 1
    for (int c = 0; c < 16; ++c) {
        CP_WAIT2();
        __syncthreads();
        if (c + 3 < 16) { ISSUE(c + 3); CP_COMMIT(); }
        else { CP_COMMIT(); }

        const char* eb = dsm + (c & 3) * EE_BUF;
        const char* bb = dsm + OFF_B + (c & 3) * B_BUF + broff;
        const char* ppc = pp_s + (pq * 2) * 1024 + c * 64;

        // ---- batch ALL operand LDS for the chunk (one latency exposure) ----
        uint2 pv[2][2], ev[2][2];   // [sub][p] / [sub][lo-hi]
#pragma unroll
        for (int sub = 0; sub < 2; ++sub) {
            const uint32_t po = (uint32_t)(sub * 32 + t * 8);
            pv[sub][0] = *(const uint2*)(ppc + po);
            pv[sub][1] = *(const uint2*)(ppc + 1024 + po);
            ev[sub][0] = *(const uint2*)(eb + r0 * 128 + aoff[sub]);
            ev[sub][1] = *(const uint2*)(eb + (r0 + 8) * 128 + aoff[sub]);
        }
        // first B quad (independent of A-build; overlaps it)
        uint4 bq = *(const uint4*)(bb + (0u ^ bxor));

        // ---- build all 16 A fragments ----
        uint32_t a[2][2][4];        // [sub][p][4]
#pragma unroll
        for (int sub = 0; sub < 2; ++sub) {
#pragma unroll
            for (int pz = 0; pz < 2; ++pz) {
                a[sub][pz][0] = hadd2_relu(ev[sub][0].x, pv[sub][pz].x);
                a[sub][pz][1] = hadd2_relu(ev[sub][1].x, pv[sub][pz].x);
                a[sub][pz][2] = hadd2_relu(ev[sub][0].y, pv[sub][pz].y);
                a[sub][pz][3] = hadd2_relu(ev[sub][1].y, pv[sub][pz].y);
            }
        }

        // ---- 32 MMAs back-to-back, B prefetched one quad ahead ----
#pragma unroll
        for (int sub = 0; sub < 2; ++sub) {
            const char* bs = bb + sub * 2048;
#pragma unroll
            for (int nip = 0; nip < 4; ++nip) {
                uint4 bq_n;
                if (nip < 3)
                    bq_n = *(const uint4*)(bs + (((uint32_t)(nip + 1) * 16u) ^ bxor));
                else if (sub == 0)
                    bq_n = *(const uint4*)(bb + 2048 + (0u ^ bxor));
                mma16(acc[2 * nip], a[sub][0], bq.x, bq.y);
                mma16(acc[2 * nip + 1], a[sub][0], bq.z, bq.w);
                mma16(acc[8 + 2 * nip], a[sub][1], bq.x, bq.y);
                mma16(acc[8 + 2 * nip + 1], a[sub][1], bq.z, bq.w);
                if (nip < 3 || sub == 0) bq = bq_n;
            }
        }
    }

    // ---- epilogue ----
    const int er0 = e0 + e_g * 16 + g;
#pragma unroll
    for (int pq2 = 0; pq2 < 2; ++pq2) {
        const size_t prow = (size_t)(p0 + pq * 2 + pq2) * E_;
        float* o0 = out + (prow + er0) * OUT_;
        float* o1 = out + (prow + er0 + 8) * OUT_;
#pragma unroll
        for (int ni = 0; ni < 8; ++ni) {
            const int ncl = ni * 8 + 2 * t;
            const int n = n0 + ncl;
            if (n < OUT_) {
                const float bz0 = bias_s[ncl], bz1 = bias_s[ncl + 1];
                const float* av = acc[pq2 * 8 + ni];
                float2 w0, w1;
                w0.x = fmaxf(av[0] + bz0, 0.0f);
                w0.y = fmaxf(av[1] + bz1, 0.0f);
                w1.x = fmaxf(av[2] + bz0, 0.0f);
                w1.y = fmaxf(av[3] + bz1, 0.0f);
                *(float2*)(o0 + n) = w0;
                *(float2*)(o1 + n) = w1;
            }
        }
    }
#undef ISSUE
}

// ---------------- launch ----------------
extern "C" void kernel_launch(void* const* d_in, const int* in_sizes, int n_in,
                              void* d_out, int out_size) {
    const float* post  = (const float*)d_in[0];
    const float* emoji = (const float*)d_in[1];
    const float* k1_w  = (const float*)d_in[2];
    const float* k1_b  = (const float*)d_in[3];
    const float* k2_w  = (const float*)d_in[4];
    const float* k2_b  = (const float*)d_in[5];
    const float* l1_w  = (const float*)d_in[6];
    const float* l1_b  = (const float*)d_in[7];
    const float* l2_w  = (const float*)d_in[8];
    const float* l2_b  = (const float*)d_in[9];
    float* out = (float*)d_out;

    __half *pPH, *pEH, *pK1, *pK2, *pL1P, *pL1E, *pPh, *pEh, *pPPH, *pEEH, *pWT;
    cudaGetSymbolAddress((void**)&pPH, g_posth);
    cudaGetSymbolAddress((void**)&pEH, g_emojih);
    cudaGetSymbolAddress((void**)&pK1, g_k1wh);
    cudaGetSymbolAddress((void**)&pK2, g_k2wh);
    cudaGetSymbolAddress((void**)&pL1P, g_l1ph);
    cudaGetSymbolAddress((void**)&pL1E, g_l1eh);
    cudaGetSymbolAddress((void**)&pPh, g_ph);
    cudaGetSymbolAddress((void**)&pEh, g_eh);
    cudaGetSymbolAddress((void**)&pPPH, g_pph);
    cudaGetSymbolAddress((void**)&pEEH, g_eeh);
    cudaGetSymbolAddress((void**)&pWT, g_wth);

    cudaFuncSetAttribute(big_kernel, cudaFuncAttributeMaxDynamicSharedMemorySize,
                         DYN_SMEM);

    prep<<<960, 256>>>(post, emoji, k1_w, k2_w, l1_w, l2_w,
                       pPH, pEH, pK1, pK2, pL1P, pL1E, pWT);
    gemm_h<<<dim3(8, 20), 256>>>(pPH, pK1, k1_b, pPh,
                                 pEH, pK2, k2_b, pEh);
    gemm_h<<<dim3(8, 20), 256>>>(pPh, pL1P, nullptr, pPPH,
                                 pEh, pL1E, l1_b, pEEH);
    big_kernel<<<8192, 256, DYN_SMEM>>>(pPPH, pEEH, pWT, l2_b, out);
}

// round 13
// speedup vs baseline: 1.5706x; 1.0110x over previous
#include <cuda_runtime.h>
#include <cuda_fp16.h>
#include <cstdint>

#define D_ 512
#define P_ 1024
#define E_ 256
#define OUT_ 500

// ---------------- device scratch ----------------
__device__ __half g_posth[P_ * D_];
__device__ __half g_emojih[E_ * D_];
__device__ __half g_k1wh[512 * 512];
__device__ __half g_k2wh[512 * 512];
__device__ __half g_l1ph[512 * 512];
__device__ __half g_l1eh[512 * 512];
__device__ __half g_ph[P_ * 512];      // p  (fp16, k-permuted)
__device__ __half g_eh[E_ * 512];      // e
__device__ __half g_pph[P_ * 512];     // pp (fp16, k-permuted)
__device__ __half g_eeh[E_ * 512];     // ee (fp16, k-permuted, +l1_b)
// l2_w frag-major tiled for 64-n tiles: [nt(8)][chunk(16)][4096B]
__device__ __half g_wth[512 * 512];

// ---------------- helpers ----------------
__device__ __forceinline__ uint32_t smem_u32(const void* p) {
    uint32_t a;
    asm("{ .reg .u64 t; cvta.to.shared.u64 t, %1; cvt.u32.u64 %0, t; }" : "=r"(a) : "l"(p));
    return a;
}
__device__ __forceinline__ void mma16(float* d, const uint32_t* a, uint32_t b0, uint32_t b1) {
    asm volatile(
        "mma.sync.aligned.m16n8k16.row.col.f32.f16.f16.f32 "
        "{%0,%1,%2,%3}, {%4,%5,%6,%7}, {%8,%9}, {%0,%1,%2,%3};"
        : "+f"(d[0]), "+f"(d[1]), "+f"(d[2]), "+f"(d[3])
        : "r"(a[0]), "r"(a[1]), "r"(a[2]), "r"(a[3]), "r"(b0), "r"(b1));
}
// relu(x + y) in packed fp16x2
__device__ __forceinline__ uint32_t hadd2_relu(uint32_t x, uint32_t y) {
    uint32_t r;
    asm("{ .reg .b32 s; add.f16x2 s, %1, %2; max.f16x2 %0, s, %3; }"
        : "=r"(r) : "r"(x), "r"(y), "r"(0u));
    return r;
}
__device__ __forceinline__ uint32_t pack_h2(float lo, float hi) {
    __half2 h = __floats2half2_rn(lo, hi);
    return *(uint32_t*)&h;
}
__device__ __forceinline__ void cp16(uint32_t s, const void* g) {
    asm volatile("cp.async.cg.shared.global [%0], [%1], 16;" :: "r"(s), "l"(g));
}
#define CP_COMMIT() asm volatile("cp.async.commit_group;" ::: "memory")
#define CP_WAIT1()  asm volatile("cp.async.wait_group 1;" ::: "memory")
#define CP_WAIT2()  asm volatile("cp.async.wait_group 2;" ::: "memory")

__device__ __forceinline__ int kperm_src(int kp) {
    int j = kp & 15, t = j >> 2, r = j & 3;
    return (kp & ~15) + 2 * t + ((r >> 1) << 3) + (r & 1);
}

// ---------------- prep (unchanged) ----------------
__global__ __launch_bounds__(256) void prep(const float* __restrict__ post,
                                            const float* __restrict__ emoji,
                                            const float* __restrict__ k1w,
                                            const float* __restrict__ k2w,
                                            const float* __restrict__ l1w,
                                            const float* __restrict__ l2w,
                                            __half* __restrict__ post_h,
                                            __half* __restrict__ emoji_h,
                                            __half* __restrict__ k1wh,
                                            __half* __restrict__ k2wh,
                                            __half* __restrict__ l1ph,
                                            __half* __restrict__ l1eh,
                                            __half* __restrict__ wth) {
#pragma unroll
    for (int it = 0; it < 8; it++) {
        int gidx = blockIdx.x * 2048 + it * 256 + threadIdx.x;
        int u = gidx;
        if (u < 524288) {
            int m = u >> 9, ks = kperm_src(u & 511);
            post_h[u] = __float2half_rn(post[m * 512 + ks]);
            continue;
        }
        u -= 524288;
        if (u < 131072) {
            int m = u >> 9, ks = kperm_src(u & 511);
            emoji_h[u] = __float2half_rn(emoji[m * 512 + ks]);
            continue;
        }
        u -= 131072;
        if (u < 262144) {
            int n = u >> 9, ks = kperm_src(u & 511);
            k1wh[u] = __float2half_rn(k1w[ks * 512 + n]);
            continue;
        }
        u -= 262144;
        if (u < 262144) {
            int n = u >> 9, ks = kperm_src(u & 511);
            k2wh[u] = __float2half_rn(k2w[ks * 512 + n]);
            continue;
        }
        u -= 262144;
        if (u < 262144) {
            int n = u >> 9, ks = kperm_src(u & 511);
            l1ph[u] = __float2half_rn(l1w[ks * 512 + n]);
            continue;
        }
        u -= 262144;
        if (u < 262144) {
            int n = u >> 9, ks = kperm_src(u & 511);
            l1eh[u] = __float2half_rn(l1w[(512 + ks) * 512 + n]);
            continue;
        }
        u -= 262144;
        {
            int nt = u >> 15;
            int rem = u & 32767;
            int c = rem >> 11;
            int byte = (rem & 2047) * 2;
            int sub = byte >> 11;
            int tt = (byte >> 9) & 3;
            int gg = (byte >> 6) & 7;
            int y = (byte & 63) ^ (tt * 16);
            int ni = y >> 3;
            int h = (y >> 1) & 3;
            int k = c * 32 + sub * 16 + 2 * tt + ((h >> 1) << 3) + (h & 1);
            int n = nt * 64 + ni * 8 + gg;
            float v = (n < OUT_) ? l2w[k * OUT_ + n] : 0.0f;
            wth[u] = __float2half_rn(v);
        }
    }
}

// ---------------- fp16 MMA GEMM for the small chain (unchanged) ----------------
#define GH_BUF 12288

__global__ __launch_bounds__(256) void gemm_h(const __half* __restrict__ A0,
                                              const __half* __restrict__ B0,
                                              const float* __restrict__ bias0,
                                              __half* __restrict__ out0,
                                              const __half* __restrict__ A1,
                                              const __half* __restrict__ B1,
                                              const float* __restrict__ bias1,
                                              __half* __restrict__ out1) {
    __shared__ __align__(16) char sm[3 * GH_BUF];
    const uint32_t sbu = smem_u32(sm);

    const int tid = threadIdx.x;
    const __half* A;
    const __half* B;
    const float* bias;
    __half* out;
    int mrow0;
    if (blockIdx.y < 16) {
        A = A0; B = B0; bias = bias0; out = out0; mrow0 = blockIdx.y * 64;
    } else {
        A = A1; B = B1; bias = bias1; out = out1; mrow0 = (blockIdx.y - 16) * 64;
    }
    const int ncol0 = blockIdx.x * 64;

    const int wid = tid >> 5, lane = tid & 31;
    const int g = lane >> 2, t = lane & 3;
    const int mgrp = wid >> 1, nw = (wid & 1) * 32;

    const int srow = tid >> 2, seg = tid & 3;
    const char* a_src = (const char*)(A + (size_t)(mrow0 + srow) * 512);
    const char* b_src = (const char*)(B + (size_t)(ncol0 + srow) * 512);
    const uint32_t a_d = srow * 96u + seg * 16u;
    const uint32_t b_d = 6144u + srow * 96u + seg * 16u;

#define GH_ISSUE(c)                                             \
    do {                                                        \
        uint32_t _b = sbu + ((c) % 3) * GH_BUF;                 \
        cp16(_b + a_d, a_src + (c) * 64 + seg * 16);            \
        cp16(_b + b_d, b_src + (c) * 64 + seg * 16);            \
    } while (0)

    GH_ISSUE(0); CP_COMMIT();
    GH_ISSUE(1); CP_COMMIT();

    float acc[4][4];
#pragma unroll
    for (int ni = 0; ni < 4; ni++)
#pragma unroll
        for (int j = 0; j < 4; j++) acc[ni][j] = 0.0f;

    const int arow = mgrp * 16 + g;

#pragma unroll 1
    for (int c = 0; c < 16; ++c) {
        CP_WAIT1();
        __syncthreads();
        if (c + 2 < 16) { GH_ISSUE(c + 2); CP_COMMIT(); }
        else { CP_COMMIT(); }

        const char* ab = sm + (c % 3) * GH_BUF;
        const char* bb = ab + 6144;
#pragma unroll
        for (int sub = 0; sub < 2; ++sub) {
            const uint32_t ko = sub * 32 + t * 8;
            const uint2 alo = *(const uint2*)(ab + arow * 96 + ko);
            const uint2 ahi = *(const uint2*)(ab + (arow + 8) * 96 + ko);
            uint32_t a[4] = {alo.x, ahi.x, alo.y, ahi.y};
#pragma unroll
            for (int ni = 0; ni < 4; ++ni) {
                const uint2 bv = *(const uint2*)(bb + (nw + ni * 8 + g) * 96 + ko);
                mma16(acc[ni], a, bv.x, bv.y);
            }
        }
    }

    const int m0 = mrow0 + mgrp * 16 + g;
#pragma unroll
    for (int ni = 0; ni < 4; ++ni) {
        const int ncol = ncol0 + nw + ni * 8;
        const int off = (ncol >> 4) * 16 + 4 * t + 2 * (ni & 1);
        const float b0v = bias ? bias[ncol + 2 * t] : 0.0f;
        const float b1v = bias ? bias[ncol + 2 * t + 1] : 0.0f;
        *(uint32_t*)(out + (size_t)m0 * 512 + off) =
            pack_h2(acc[ni][0] + b0v, acc[ni][1] + b1v);
        *(uint32_t*)(out + (size_t)(m0 + 8) * 512 + off) =
            pack_h2(acc[ni][2] + b0v, acc[ni][3] + b1v);
    }
#undef GH_ISSUE
}

// ---------------- main kernel ----------------
// CTA = (4p, 64e, 64n), 256 thr = 8 warps = 2 p-pairs x 4 e-groups.
// Chunk-PAIR pipeline: one barrier per 2 chunks; chunk1 operand LDS overlaps
// chunk0 MMAs. ee in 64B rows, XOR X(row)=(row&1)*32 (conflict-free both ways).
// 8 chunk buffers (4 pair slots), 2 CTAs/SM. grid 8192.
#define EE_BUF 4096u
#define B_BUF  4096u
#define OFF_B  (8 * EE_BUF)           // 32768
#define OFF_PP (OFF_B + 8 * B_BUF)    // 65536
#define OFF_BI (OFF_PP + 4096u)       // 69632
#define DYN_SMEM (OFF_BI + 256u)      // 69888

__global__ __launch_bounds__(256, 2) void big_kernel(const __half* __restrict__ pp,
                                                     const __half* __restrict__ ee,
                                                     const __half* __restrict__ wth,
                                                     const float* __restrict__ bias,
                                                     float* __restrict__ out) {
    extern __shared__ char dsm[];
    const uint32_t sbu = smem_u32(dsm);

    const int tid = threadIdx.x;
    const int bid = blockIdx.x;
    const int nt = bid & 7, eq = (bid >> 3) & 3, pg = bid >> 5;
    const int n0 = nt * 64, e0 = eq * 64, p0 = pg * 4;

    const int wid = tid >> 5, lane = tid & 31;
    const int g = lane >> 2, t = lane & 3;
    const int pq = wid >> 2;        // p-pair 0/1
    const int e_g = wid & 3;        // 0..3

    // ---- staging ----
    const int srow = tid >> 2;                   // 0..63
    const int seg = tid & 3;
    const char* ee_src = (const char*)(ee + (size_t)(e0 + srow) * 512);
    const char* wt_src = (const char*)(wth + (size_t)nt * 32768);
    const uint32_t exw = ((uint32_t)(srow & 1)) * 32u;
    const uint32_t ee_d = srow * 64u + (((uint32_t)seg * 16u) ^ exw);
    const uint32_t b_d = OFF_B + (uint32_t)tid * 16u;

#define ISSUE(c)                                                        \
    do {                                                                \
        uint32_t _st = ((c) & 7);                                       \
        cp16(sbu + _st * EE_BUF + ee_d, ee_src + (c) * 64 + seg * 16);  \
        cp16(sbu + _st * B_BUF + b_d, wt_src + (c) * 4096 + tid * 16);  \
    } while (0)

    ISSUE(0); ISSUE(1); CP_COMMIT();
    ISSUE(2); ISSUE(3); CP_COMMIT();
    ISSUE(4); ISSUE(5); CP_COMMIT();

    // pp (fp16 permuted, 4 rows = 4096B) + bias
    char* pp_s = dsm + OFF_PP;
    float* bias_s = (float*)(dsm + OFF_BI);
    ((uint4*)pp_s)[tid] = ((const uint4*)(pp + (size_t)p0 * 512))[tid];
    if (tid < 64) bias_s[tid] = (n0 + tid < OUT_) ? bias[n0 + tid] : 0.0f;

    float acc[16][4];   // [p(2)][ni(8)][4]
#pragma unroll
    for (int ni = 0; ni < 16; ni++)
#pragma unroll
        for (int j = 0; j < 4; j++) acc[ni][j] = 0.0f;

    // read-side constants
    const int r0 = e_g * 16 + g;
    const uint32_t axor = ((uint32_t)(g & 1)) * 32u;
    const uint32_t aoff[2] = {((uint32_t)(0 * 32 + t * 8)) ^ axor,
                              ((uint32_t)(1 * 32 + t * 8)) ^ axor};
    const uint32_t broff = (uint32_t)(t * 512 + g * 64);
    const uint32_t bxor = (uint32_t)(t * 16);

#define MMA_CHUNK(bbX, aX)                                                        \
    do {                                                                          \
        uint4 bq = *(const uint4*)((bbX) + (0u ^ bxor));                          \
        _Pragma("unroll")                                                         \
        for (int sub = 0; sub < 2; ++sub) {                                       \
            const char* bs = (bbX) + sub * 2048;                                  \
            _Pragma("unroll")                                                     \
            for (int nip = 0; nip < 4; ++nip) {                                   \
                uint4 bq_n;                                                       \
                if (nip < 3)                                                      \
                    bq_n = *(const uint4*)(bs + (((uint32_t)(nip + 1) * 16u) ^ bxor)); \
                else if (sub == 0)                                                \
                    bq_n = *(const uint4*)((bbX) + 2048 + (0u ^ bxor));           \
                mma16(acc[2 * nip], aX[sub][0], bq.x, bq.y);                      \
                mma16(acc[2 * nip + 1], aX[sub][0], bq.z, bq.w);                  \
                mma16(acc[8 + 2 * nip], aX[sub][1], bq.x, bq.y);                  \
                mma16(acc[8 + 2 * nip + 1], aX[sub][1], bq.z, bq.w);              \
                if (nip < 3 || sub == 0) bq = bq_n;                               \
            }                                                                     \
        }                                                                         \
    } while (0)

#pragma unroll 1
    for (int cp = 0; cp < 8; ++cp) {
        CP_WAIT2();
        __syncthreads();
        if (cp + 3 < 8) { ISSUE(2 * (cp + 3)); ISSUE(2 * (cp + 3) + 1); CP_COMMIT(); }
        else { CP_COMMIT(); }

        const int c0 = 2 * cp, c1 = c0 + 1;
        const char* ebA = dsm + (c0 & 7) * EE_BUF;
        const char* ebB = dsm + (c1 & 7) * EE_BUF;
        const char* bbA = dsm + OFF_B + (c0 & 7) * B_BUF + broff;
        const char* bbB = dsm + OFF_B + (c1 & 7) * B_BUF + broff;
        const char* ppcA = pp_s + (pq * 2) * 1024 + c0 * 64;
        const char* ppcB = ppcA + 64;

        // ---- chunk A: operands + A-build ----
        uint2 pvA[2][2], evA[2][2];
#pragma unroll
        for (int sub = 0; sub < 2; ++sub) {
            const uint32_t po = (uint32_t)(sub * 32 + t * 8);
            pvA[sub][0] = *(const uint2*)(ppcA + po);
            pvA[sub][1] = *(const uint2*)(ppcA + 1024 + po);
            evA[sub][0] = *(const uint2*)(ebA + r0 * 64 + aoff[sub]);
            evA[sub][1] = *(const uint2*)(ebA + (r0 + 8) * 64 + aoff[sub]);
        }
        uint32_t aA[2][2][4];
#pragma unroll
        for (int sub = 0; sub < 2; ++sub)
#pragma unroll
            for (int pz = 0; pz < 2; ++pz) {
                aA[sub][pz][0] = hadd2_relu(evA[sub][0].x, pvA[sub][pz].x);
                aA[sub][pz][1] = hadd2_relu(evA[sub][1].x, pvA[sub][pz].x);
                aA[sub][pz][2] = hadd2_relu(evA[sub][0].y, pvA[sub][pz].y);
                aA[sub][pz][3] = hadd2_relu(evA[sub][1].y, pvA[sub][pz].y);
            }

        // ---- chunk B operand LDS issued here; latency covered by MMA A ----
        uint2 pvB[2][2], evB[2][2];
#pragma unroll
        for (int sub = 0; sub < 2; ++sub) {
            const uint32_t po = (uint32_t)(sub * 32 + t * 8);
            pvB[sub][0] = *(const uint2*)(ppcB + po);
            pvB[sub][1] = *(const uint2*)(ppcB + 1024 + po);
            evB[sub][0] = *(const uint2*)(ebB + r0 * 64 + aoff[sub]);
            evB[sub][1] = *(const uint2*)(ebB + (r0 + 8) * 64 + aoff[sub]);
        }

        // ---- MMA chunk A ----
        MMA_CHUNK(bbA, aA);

        // ---- build chunk B A-fragments, then MMA chunk B ----
        uint32_t aB[2][2][4];
#pragma unroll
        for (int sub = 0; sub < 2; ++sub)
#pragma unroll
            for (int pz = 0; pz < 2; ++pz) {
                aB[sub][pz][0] = hadd2_relu(evB[sub][0].x, pvB[sub][pz].x);
                aB[sub][pz][1] = hadd2_relu(evB[sub][1].x, pvB[sub][pz].x);
                aB[sub][pz][2] = hadd2_relu(evB[sub][0].y, pvB[sub][pz].y);
                aB[sub][pz][3] = hadd2_relu(evB[sub][1].y, pvB[sub][pz].y);
            }
        MMA_CHUNK(bbB, aB);
    }

    // ---- epilogue ----
    const int er0 = e0 + e_g * 16 + g;
#pragma unroll
    for (int pq2 = 0; pq2 < 2; ++pq2) {
        const size_t prow = (size_t)(p0 + pq * 2 + pq2) * E_;
        float* o0 = out + (prow + er0) * OUT_;
        float* o1 = out + (prow + er0 + 8) * OUT_;
#pragma unroll
        for (int ni = 0; ni < 8; ++ni) {
            const int ncl = ni * 8 + 2 * t;
            const int n = n0 + ncl;
            if (n < OUT_) {
                const float bz0 = bias_s[ncl], bz1 = bias_s[ncl + 1];
                const float* av = acc[pq2 * 8 + ni];
                float2 w0, w1;
                w0.x = fmaxf(av[0] + bz0, 0.0f);
                w0.y = fmaxf(av[1] + bz1, 0.0f);
                w1.x = fmaxf(av[2] + bz0, 0.0f);
                w1.y = fmaxf(av[3] + bz1, 0.0f);
                *(float2*)(o0 + n) = w0;
                *(float2*)(o1 + n) = w1;
            }
        }
    }
#undef ISSUE
#undef MMA_CHUNK
}

// ---------------- launch ----------------
extern "C" void kernel_launch(void* const* d_in, const int* in_sizes, int n_in,
                              void* d_out, int out_size) {
    const float* post  = (const float*)d_in[0];
    const float* emoji = (const float*)d_in[1];
    const float* k1_w  = (const float*)d_in[2];
    const float* k1_b  = (const float*)d_in[3];
    const float* k2_w  = (const float*)d_in[4];
    const float* k2_b  = (const float*)d_in[5];
    const float* l1_w  = (const float*)d_in[6];
    const float* l1_b  = (const float*)d_in[7];
    const float* l2_w  = (const float*)d_in[8];
    const float* l2_b  = (const float*)d_in[9];
    float* out = (float*)d_out;

    __half *pPH, *pEH, *pK1, *pK2, *pL1P, *pL1E, *pPh, *pEh, *pPPH, *pEEH, *pWT;
    cudaGetSymbolAddress((void**)&pPH, g_posth);
    cudaGetSymbolAddress((void**)&pEH, g_emojih);
    cudaGetSymbolAddress((void**)&pK1, g_k1wh);
    cudaGetSymbolAddress((void**)&pK2, g_k2wh);
    cudaGetSymbolAddress((void**)&pL1P, g_l1ph);
    cudaGetSymbolAddress((void**)&pL1E, g_l1eh);
    cudaGetSymbolAddress((void**)&pPh, g_ph);
    cudaGetSymbolAddress((void**)&pEh, g_eh);
    cudaGetSymbolAddress((void**)&pPPH, g_pph);
    cudaGetSymbolAddress((void**)&pEEH, g_eeh);
    cudaGetSymbolAddress((void**)&pWT, g_wth);

    cudaFuncSetAttribute(big_kernel, cudaFuncAttributeMaxDynamicSharedMemorySize,
                         DYN_SMEM);

    prep<<<960, 256>>>(post, emoji, k1_w, k2_w, l1_w, l2_w,
                       pPH, pEH, pK1, pK2, pL1P, pL1E, pWT);
    gemm_h<<<dim3(8, 20), 256>>>(pPH, pK1, k1_b, pPh,
                                 pEH, pK2, k2_b, pEh);
    gemm_h<<<dim3(8, 20), 256>>>(pPh, pL1P, nullptr, pPPH,
                                 pEh, pL1E, l1_b, pEEH);
    big_kernel<<<8192, 256, DYN_SMEM>>>(pPPH, pEEH, pWT, l2_b, out);
}

// round 15
// speedup vs baseline: 1.5958x; 1.0160x over previous
#include <cuda_runtime.h>
#include <cuda_fp16.h>
#include <cstdint>

#define D_ 512
#define P_ 1024
#define E_ 256
#define OUT_ 500

// ---------------- device scratch ----------------
__device__ __half g_posth[P_ * D_];
__device__ __half g_emojih[E_ * D_];
__device__ __half g_k1wh[512 * 512];
__device__ __half g_k2wh[512 * 512];
__device__ __half g_l1ph[512 * 512];
__device__ __half g_l1eh[512 * 512];
__device__ __half g_ph[P_ * 512];      // p  (fp16, k-permuted)
__device__ __half g_eh[E_ * 512];      // e
__device__ __half g_pph[P_ * 512];     // pp (fp16, k-permuted)
__device__ __half g_eeh[E_ * 512];     // ee (fp16, k-permuted, +l1_b)
// l2_w frag-direct tiled for 64-n tiles: [nt(8)][chunk(16)][4096B]
// chunk byte: sub*2048 + ni*256 + (g*4+t)*8, frag = 8B = k-pairs {2t,2t+1,2t+8,2t+9}
__device__ __half g_wth[512 * 512];

// ---------------- helpers ----------------
__device__ __forceinline__ uint32_t smem_u32(const void* p) {
    uint32_t a;
    asm("{ .reg .u64 t; cvta.to.shared.u64 t, %1; cvt.u32.u64 %0, t; }" : "=r"(a) : "l"(p));
    return a;
}
__device__ __forceinline__ void mma16(float* d, const uint32_t* a, uint32_t b0, uint32_t b1) {
    asm volatile(
        "mma.sync.aligned.m16n8k16.row.col.f32.f16.f16.f32 "
        "{%0,%1,%2,%3}, {%4,%5,%6,%7}, {%8,%9}, {%0,%1,%2,%3};"
        : "+f"(d[0]), "+f"(d[1]), "+f"(d[2]), "+f"(d[3])
        : "r"(a[0]), "r"(a[1]), "r"(a[2]), "r"(a[3]), "r"(b0), "r"(b1));
}
// relu(x + y) in packed fp16x2
__device__ __forceinline__ uint32_t hadd2_relu(uint32_t x, uint32_t y) {
    uint32_t r;
    asm("{ .reg .b32 s; add.f16x2 s, %1, %2; max.f16x2 %0, s, %3; }"
        : "=r"(r) : "r"(x), "r"(y), "r"(0u));
    return r;
}
__device__ __forceinline__ uint32_t pack_h2(float lo, float hi) {
    __half2 h = __floats2half2_rn(lo, hi);
    return *(uint32_t*)&h;
}
__device__ __forceinline__ void cp16(uint32_t s, const void* g) {
    asm volatile("cp.async.cg.shared.global [%0], [%1], 16;" :: "r"(s), "l"(g));
}
#define CP_COMMIT() asm volatile("cp.async.commit_group;" ::: "memory")
#define CP_WAIT1()  asm volatile("cp.async.wait_group 1;" ::: "memory")
#define CP_WAIT2()  asm volatile("cp.async.wait_group 2;" ::: "memory")

__device__ __forceinline__ int kperm_src(int kp) {
    int j = kp & 15, t = j >> 2, r = j & 3;
    return (kp & ~15) + 2 * t + ((r >> 1) << 3) + (r & 1);
}

// ---------------- prep ----------------
__global__ __launch_bounds__(256) void prep(const float* __restrict__ post,
                                            const float* __restrict__ emoji,
                                            const float* __restrict__ k1w,
                                            const float* __restrict__ k2w,
                                            const float* __restrict__ l1w,
                                            const float* __restrict__ l2w,
                                            __half* __restrict__ post_h,
                                            __half* __restrict__ emoji_h,
                                            __half* __restrict__ k1wh,
                                            __half* __restrict__ k2wh,
                                            __half* __restrict__ l1ph,
                                            __half* __restrict__ l1eh,
                                            __half* __restrict__ wth) {
#pragma unroll
    for (int it = 0; it < 8; it++) {
        int gidx = blockIdx.x * 2048 + it * 256 + threadIdx.x;
        int u = gidx;
        if (u < 524288) {
            int m = u >> 9, ks = kperm_src(u & 511);
            post_h[u] = __float2half_rn(post[m * 512 + ks]);
            continue;
        }
        u -= 524288;
        if (u < 131072) {
            int m = u >> 9, ks = kperm_src(u & 511);
            emoji_h[u] = __float2half_rn(emoji[m * 512 + ks]);
            continue;
        }
        u -= 131072;
        if (u < 262144) {
            int n = u >> 9, ks = kperm_src(u & 511);
            k1wh[u] = __float2half_rn(k1w[ks * 512 + n]);
            continue;
        }
        u -= 262144;
        if (u < 262144) {
            int n = u >> 9, ks = kperm_src(u & 511);
            k2wh[u] = __float2half_rn(k2w[ks * 512 + n]);
            continue;
        }
        u -= 262144;
        if (u < 262144) {
            int n = u >> 9, ks = kperm_src(u & 511);
            l1ph[u] = __float2half_rn(l1w[ks * 512 + n]);
            continue;
        }
        u -= 262144;
        if (u < 262144) {
            int n = u >> 9, ks = kperm_src(u & 511);
            l1eh[u] = __float2half_rn(l1w[(512 + ks) * 512 + n]);
            continue;
        }
        u -= 262144;
        {
            // frag-direct layout: byte = sub*2048 + ni*256 + (g*4+t)*8 + h*2
            int nt = u >> 15;
            int rem = u & 32767;
            int c = rem >> 11;
            int byte = (rem & 2047) * 2;
            int sub = byte >> 11;
            int q = byte & 2047;
            int ni = q >> 8;
            int fr = (q >> 3) & 31;
            int gg = fr >> 2;
            int tt = fr & 3;
            int h = (byte >> 1) & 3;
            int k = c * 32 + sub * 16 + 2 * tt + ((h >> 1) << 3) + (h & 1);
            int n = nt * 64 + ni * 8 + gg;
            float v = (n < OUT_) ? l2w[k * OUT_ + n] : 0.0f;
            wth[u] = __float2half_rn(v);
        }
    }
}

// ---------------- fp16 MMA GEMM for the small chain (unchanged) ----------------
#define GH_BUF 12288

__global__ __launch_bounds__(256) void gemm_h(const __half* __restrict__ A0,
                                              const __half* __restrict__ B0,
                                              const float* __restrict__ bias0,
                                              __half* __restrict__ out0,
                                              const __half* __restrict__ A1,
                                              const __half* __restrict__ B1,
                                              const float* __restrict__ bias1,
                                              __half* __restrict__ out1) {
    __shared__ __align__(16) char sm[3 * GH_BUF];
    const uint32_t sbu = smem_u32(sm);

    const int tid = threadIdx.x;
    const __half* A;
    const __half* B;
    const float* bias;
    __half* out;
    int mrow0;
    if (blockIdx.y < 16) {
        A = A0; B = B0; bias = bias0; out = out0; mrow0 = blockIdx.y * 64;
    } else {
        A = A1; B = B1; bias = bias1; out = out1; mrow0 = (blockIdx.y - 16) * 64;
    }
    const int ncol0 = blockIdx.x * 64;

    const int wid = tid >> 5, lane = tid & 31;
    const int g = lane >> 2, t = lane & 3;
    const int mgrp = wid >> 1, nw = (wid & 1) * 32;

    const int srow = tid >> 2, seg = tid & 3;
    const char* a_src = (const char*)(A + (size_t)(mrow0 + srow) * 512);
    const char* b_src = (const char*)(B + (size_t)(ncol0 + srow) * 512);
    const uint32_t a_d = srow * 96u + seg * 16u;
    const uint32_t b_d = 6144u + srow * 96u + seg * 16u;

#define GH_ISSUE(c)                                             \
    do {                                                        \
        uint32_t _b = sbu + ((c) % 3) * GH_BUF;                 \
        cp16(_b + a_d, a_src + (c) * 64 + seg * 16);            \
        cp16(_b + b_d, b_src + (c) * 64 + seg * 16);            \
    } while (0)

    GH_ISSUE(0); CP_COMMIT();
    GH_ISSUE(1); CP_COMMIT();

    float acc[4][4];
#pragma unroll
    for (int ni = 0; ni < 4; ni++)
#pragma unroll
        for (int j = 0; j < 4; j++) acc[ni][j] = 0.0f;

    const int arow = mgrp * 16 + g;

#pragma unroll 1
    for (int c = 0; c < 16; ++c) {
        CP_WAIT1();
        __syncthreads();
        if (c + 2 < 16) { GH_ISSUE(c + 2); CP_COMMIT(); }
        else { CP_COMMIT(); }

        const char* ab = sm + (c % 3) * GH_BUF;
        const char* bb = ab + 6144;
#pragma unroll
        for (int sub = 0; sub < 2; ++sub) {
            const uint32_t ko = sub * 32 + t * 8;
            const uint2 alo = *(const uint2*)(ab + arow * 96 + ko);
            const uint2 ahi = *(const uint2*)(ab + (arow + 8) * 96 + ko);
            uint32_t a[4] = {alo.x, ahi.x, alo.y, ahi.y};
#pragma unroll
            for (int ni = 0; ni < 4; ++ni) {
                const uint2 bv = *(const uint2*)(bb + (nw + ni * 8 + g) * 96 + ko);
                mma16(acc[ni], a, bv.x, bv.y);
            }
        }
    }

    const int m0 = mrow0 + mgrp * 16 + g;
#pragma unroll
    for (int ni = 0; ni < 4; ++ni) {
        const int ncol = ncol0 + nw + ni * 8;
        const int off = (ncol >> 4) * 16 + 4 * t + 2 * (ni & 1);
        const float b0v = bias ? bias[ncol + 2 * t] : 0.0f;
        const float b1v = bias ? bias[ncol + 2 * t + 1] : 0.0f;
        *(uint32_t*)(out + (size_t)m0 * 512 + off) =
            pack_h2(acc[ni][0] + b0v, acc[ni][1] + b1v);
        *(uint32_t*)(out + (size_t)(m0 + 8) * 512 + off) =
            pack_h2(acc[ni][2] + b0v, acc[ni][3] + b1v);
    }
#undef GH_ISSUE
}

// ---------------- main kernel ----------------
// CTA = (4p, 64e, 64n), 256 thr = 8 warps = 2 p-pairs x 4 e-groups.
// Chunk-pair pipeline; B in frag-direct layout -> one LDS.64 per MMA pair,
// no register rotation. ee 64B rows XOR (row&1)*32. 8 buffers, 2 CTAs/SM.
#define EE_BUF 4096u
#define B_BUF  4096u
#define OFF_B  (8 * EE_BUF)           // 32768
#define OFF_PP (OFF_B + 8 * B_BUF)    // 65536
#define OFF_BI (OFF_PP + 4096u)       // 69632
#define DYN_SMEM (OFF_BI + 256u)      // 69888

__global__ __launch_bounds__(256, 2) void big_kernel(const __half* __restrict__ pp,
                                                     const __half* __restrict__ ee,
                                                     const __half* __restrict__ wth,
                                                     const float* __restrict__ bias,
                                                     float* __restrict__ out) {
    extern __shared__ char dsm[];
    const uint32_t sbu = smem_u32(dsm);

    const int tid = threadIdx.x;
    const int bid = blockIdx.x;
    const int nt = bid & 7, eq = (bid >> 3) & 3, pg = bid >> 5;
    const int n0 = nt * 64, e0 = eq * 64, p0 = pg * 4;

    const int wid = tid >> 5, lane = tid & 31;
    const int g = lane >> 2, t = lane & 3;
    const int pq = wid >> 2;        // p-pair 0/1
    const int e_g = wid & 3;        // 0..3

    // ---- staging ----
    const int srow = tid >> 2;                   // 0..63
    const int seg = tid & 3;
    const char* ee_src = (const char*)(ee + (size_t)(e0 + srow) * 512);
    const char* wt_src = (const char*)(wth + (size_t)nt * 32768);
    const uint32_t exw = ((uint32_t)(srow & 1)) * 32u;
    const uint32_t ee_d = srow * 64u + (((uint32_t)seg * 16u) ^ exw);
    const uint32_t b_d = OFF_B + (uint32_t)tid * 16u;

#define ISSUE(c)                                                        \
    do {                                                                \
        uint32_t _st = ((c) & 7);                                       \
        cp16(sbu + _st * EE_BUF + ee_d, ee_src + (c) * 64 + seg * 16);  \
        cp16(sbu + _st * B_BUF + b_d, wt_src + (c) * 4096 + tid * 16);  \
    } while (0)

    ISSUE(0); ISSUE(1); CP_COMMIT();
    ISSUE(2); ISSUE(3); CP_COMMIT();
    ISSUE(4); ISSUE(5); CP_COMMIT();

    // pp (fp16 permuted, 4 rows = 4096B) + bias
    char* pp_s = dsm + OFF_PP;
    float* bias_s = (float*)(dsm + OFF_BI);
    ((uint4*)pp_s)[tid] = ((const uint4*)(pp + (size_t)p0 * 512))[tid];
    if (tid < 64) bias_s[tid] = (n0 + tid < OUT_) ? bias[n0 + tid] : 0.0f;

    float acc[16][4];   // [p(2)][ni(8)][4]
#pragma unroll
    for (int ni = 0; ni < 16; ni++)
#pragma unroll
        for (int j = 0; j < 4; j++) acc[ni][j] = 0.0f;

    // read-side constants
    const int r0 = e_g * 16 + g;
    const uint32_t axor = ((uint32_t)(g & 1)) * 32u;
    const uint32_t aoff[2] = {((uint32_t)(0 * 32 + t * 8)) ^ axor,
                              ((uint32_t)(1 * 32 + t * 8)) ^ axor};
    const uint32_t fr8 = (uint32_t)((g * 4 + t) * 8);   // frag offset in B layout

#define MMA_CHUNK(bbX, aX)                                                \
    do {                                                                  \
        _Pragma("unroll")                                                 \
        for (int sub = 0; sub < 2; ++sub) {                               \
            const char* bs = (bbX) + sub * 2048 + fr8;                    \
            _Pragma("unroll")                                             \
            for (int ni = 0; ni < 8; ++ni) {                              \
                const uint2 bv = *(const uint2*)(bs + ni * 256);          \
                mma16(acc[ni], aX[sub][0], bv.x, bv.y);                   \
                mma16(acc[8 + ni], aX[sub][1], bv.x, bv.y);               \
            }                                                             \
        }                                                                 \
    } while (0)

#pragma unroll 1
    for (int cp = 0; cp < 8; ++cp) {
        CP_WAIT2();
        __syncthreads();
        if (cp + 3 < 8) { ISSUE(2 * (cp + 3)); ISSUE(2 * (cp + 3) + 1); CP_COMMIT(); }
        else { CP_COMMIT(); }

        const int c0 = 2 * cp, c1 = c0 + 1;
        const char* ebA = dsm + (c0 & 7) * EE_BUF;
        const char* ebB = dsm + (c1 & 7) * EE_BUF;
        const char* bbA = dsm + OFF_B + (c0 & 7) * B_BUF;
        const char* bbB = dsm + OFF_B + (c1 & 7) * B_BUF;
        const char* ppcA = pp_s + (pq * 2) * 1024 + c0 * 64;
        const char* ppcB = ppcA + 64;

        // ---- chunk A: operands + A-build ----
        uint2 pvA[2][2], evA[2][2];
#pragma unroll
        for (int sub = 0; sub < 2; ++sub) {
            const uint32_t po = (uint32_t)(sub * 32 + t * 8);
            pvA[sub][0] = *(const uint2*)(ppcA + po);
            pvA[sub][1] = *(const uint2*)(ppcA + 1024 + po);
            evA[sub][0] = *(const uint2*)(ebA + r0 * 64 + aoff[sub]);
            evA[sub][1] = *(const uint2*)(ebA + (r0 + 8) * 64 + aoff[sub]);
        }
        uint32_t aA[2][2][4];
#pragma unroll
        for (int sub = 0; sub < 2; ++sub)
#pragma unroll
            for (int pz = 0; pz < 2; ++pz) {
                aA[sub][pz][0] = hadd2_relu(evA[sub][0].x, pvA[sub][pz].x);
                aA[sub][pz][1] = hadd2_relu(evA[sub][1].x, pvA[sub][pz].x);
                aA[sub][pz][2] = hadd2_relu(evA[sub][0].y, pvA[sub][pz].y);
                aA[sub][pz][3] = hadd2_relu(evA[sub][1].y, pvA[sub][pz].y);
            }

        // ---- chunk B operand LDS issued here; latency covered by MMA A ----
        uint2 pvB[2][2], evB[2][2];
#pragma unroll
        for (int sub = 0; sub < 2; ++sub) {
            const uint32_t po = (uint32_t)(sub * 32 + t * 8);
            pvB[sub][0] = *(const uint2*)(ppcB + po);
            pvB[sub][1] = *(const uint2*)(ppcB + 1024 + po);
            evB[sub][0] = *(const uint2*)(ebB + r0 * 64 + aoff[sub]);
            evB[sub][1] = *(const uint2*)(ebB + (r0 + 8) * 64 + aoff[sub]);
        }

        // ---- MMA chunk A ----
        MMA_CHUNK(bbA, aA);

        // ---- build chunk B A-fragments, then MMA chunk B ----
        uint32_t aB[2][2][4];
#pragma unroll
        for (int sub = 0; sub < 2; ++sub)
#pragma unroll
            for (int pz = 0; pz < 2; ++pz) {
                aB[sub][pz][0] = hadd2_relu(evB[sub][0].x, pvB[sub][pz].x);
                aB[sub][pz][1] = hadd2_relu(evB[sub][1].x, pvB[sub][pz].x);
                aB[sub][pz][2] = hadd2_relu(evB[sub][0].y, pvB[sub][pz].y);
                aB[sub][pz][3] = hadd2_relu(evB[sub][1].y, pvB[sub][pz].y);
            }
        MMA_CHUNK(bbB, aB);
    }

    // ---- epilogue ----
    const int er0 = e0 + e_g * 16 + g;
#pragma unroll
    for (int pq2 = 0; pq2 < 2; ++pq2) {
        const size_t prow = (size_t)(p0 + pq * 2 + pq2) * E_;
        float* o0 = out + (prow + er0) * OUT_;
        float* o1 = out + (prow + er0 + 8) * OUT_;
#pragma unroll
        for (int ni = 0; ni < 8; ++ni) {
            const int ncl = ni * 8 + 2 * t;
            const int n = n0 + ncl;
            if (n < OUT_) {
                const float bz0 = bias_s[ncl], bz1 = bias_s[ncl + 1];
                const float* av = acc[pq2 * 8 + ni];
                float2 w0, w1;
                w0.x = fmaxf(av[0] + bz0, 0.0f);
                w0.y = fmaxf(av[1] + bz1, 0.0f);
                w1.x = fmaxf(av[2] + bz0, 0.0f);
                w1.y = fmaxf(av[3] + bz1, 0.0f);
                *(float2*)(o0 + n) = w0;
                *(float2*)(o1 + n) = w1;
            }
        }
    }
#undef ISSUE
#undef MMA_CHUNK
}

// ---------------- launch ----------------
extern "C" void kernel_launch(void* const* d_in, const int* in_sizes, int n_in,
                              void* d_out, int out_size) {
    const float* post  = (const float*)d_in[0];
    const float* emoji = (const float*)d_in[1];
    const float* k1_w  = (const float*)d_in[2];
    const float* k1_b  = (const float*)d_in[3];
    const float* k2_w  = (const float*)d_in[4];
    const float* k2_b  = (const float*)d_in[5];
    const float* l1_w  = (const float*)d_in[6];
    const float* l1_b  = (const float*)d_in[7];
    const float* l2_w  = (const float*)d_in[8];
    const float* l2_b  = (const float*)d_in[9];
    float* out = (float*)d_out;

    __half *pPH, *pEH, *pK1, *pK2, *pL1P, *pL1E, *pPh, *pEh, *pPPH, *pEEH, *pWT;
    cudaGetSymbolAddress((void**)&pPH, g_posth);
    cudaGetSymbolAddress((void**)&pEH, g_emojih);
    cudaGetSymbolAddress((void**)&pK1, g_k1wh);
    cudaGetSymbolAddress((void**)&pK2, g_k2wh);
    cudaGetSymbolAddress((void**)&pL1P, g_l1ph);
    cudaGetSymbolAddress((void**)&pL1E, g_l1eh);
    cudaGetSymbolAddress((void**)&pPh, g_ph);
    cudaGetSymbolAddress((void**)&pEh, g_eh);
    cudaGetSymbolAddress((void**)&pPPH, g_pph);
    cudaGetSymbolAddress((void**)&pEEH, g_eeh);
    cudaGetSymbolAddress((void**)&pWT, g_wth);

    cudaFuncSetAttribute(big_kernel, cudaFuncAttributeMaxDynamicSharedMemorySize,
                         DYN_SMEM);

    prep<<<960, 256>>>(post, emoji, k1_w, k2_w, l1_w, l2_w,
                       pPH, pEH, pK1, pK2, pL1P, pL1E, pWT);
    gemm_h<<<dim3(8, 20), 256>>>(pPH, pK1, k1_b, pPh,
                                 pEH, pK2, k2_b, pEh);
    gemm_h<<<dim3(8, 20), 256>>>(pPh, pL1P, nullptr, pPPH,
                                 pEh, pL1E, l1_b, pEEH);
    big_kernel<<<8192, 256, DYN_SMEM>>>(pPPH, pEEH, pWT, l2_b, out);
}